// round 1
// baseline (speedup 1.0000x reference)
#include <cuda_runtime.h>
#include <stdint.h>

// ---------------- problem constants (fixed shapes for this problem) ----------------
#define NN      100000
#define DD      256
#define VV      3
#define PP      1024
#define NEGN    1024
#define UU      2048
#define MM      6144          // rows in each similarity matrix (2048*3)
#define LABSPLIT 3072         // rows < 3072 have label 1 (pos nodes first)
#define NSPLIT  3
#define JCHUNK  (MM / NSPLIT) // 2048
#define TI      128
#define TJ      128
#define KC      32
#define PAD     132           // padded smem row to avoid bank conflicts, keeps 16B align
#define BCE_BLOCKS 128

// ---------------- device scratch (no cudaMalloc allowed) ----------------
__device__ float4 g_zv[2][MM][DD / 4];          // [0]=sup zf, [1]=unsup zn (renormalized)
__device__ float  g_s[2][NSPLIT][MM];           // per-row sum of exp(5*dot - OFF)
__device__ float  g_t[NSPLIT][MM];              // per-row sum of dot over same-label cols (sup)
__device__ float  g_bce_part[BCE_BLOCKS][5];    // main, v0, v1, v2, mask_count
__device__ float  g_sup_part[24];
__device__ float  g_un_part[256];
__device__ int    g_maskmode;                   // 0=int32, 1=uint8/bool, 2=float32

// ---------------- packed f32x2 helpers ----------------
__device__ __forceinline__ unsigned long long ffma2(unsigned long long a,
                                                    unsigned long long b,
                                                    unsigned long long c) {
    unsigned long long d;
    asm("fma.rn.f32x2 %0, %1, %2, %3;" : "=l"(d) : "l"(a), "l"(b), "l"(c));
    return d;
}
__device__ __forceinline__ unsigned long long pk2(float lo, float hi) {
    unsigned long long d;
    asm("mov.b64 %0, {%1, %2};" : "=l"(d) : "r"(__float_as_uint(lo)), "r"(__float_as_uint(hi)));
    return d;
}
__device__ __forceinline__ void upk2(unsigned long long v, float& lo, float& hi) {
    unsigned int a, b;
    asm("mov.b64 {%0, %1}, %2;" : "=r"(a), "=r"(b) : "l"(v));
    lo = __uint_as_float(a); hi = __uint_as_float(b);
}

// deterministic block reduce (blockDim.x == 256)
__device__ __forceinline__ float blk_reduce(float v, float* sm) {
    int tid = threadIdx.x;
    sm[tid] = v; __syncthreads();
#pragma unroll
    for (int s = 128; s > 0; s >>= 1) {
        if (tid < s) sm[tid] += sm[tid + s];
        __syncthreads();
    }
    float r = sm[0]; __syncthreads();
    return r;
}

// ---------------- mask dtype detection ----------------
__global__ void detect_mask_kernel(const unsigned char* m) {
    if (threadIdx.x == 0 && blockIdx.x == 0) {
        bool nonbin = false, oddone = false;
        for (int i = 0; i < 256; i++) {
            unsigned char b = m[i];
            if (b > 1) nonbin = true;
            else if (b == 1 && (i & 3)) oddone = true;
        }
        g_maskmode = nonbin ? 2 : (oddone ? 1 : 0);
    }
}

// ---------------- BCE partial sums ----------------
__global__ void __launch_bounds__(256) bce_kernel(const float* __restrict__ fused,
                                                  const float* __restrict__ vlg,
                                                  const float* __restrict__ lab,
                                                  const void* __restrict__ maskp,
                                                  int n) {
    __shared__ float sm[256];
    int mode = g_maskmode;
    float s_main = 0.f, s_v0 = 0.f, s_v1 = 0.f, s_v2 = 0.f, s_cnt = 0.f;
    for (int i = blockIdx.x * blockDim.x + threadIdx.x; i < n; i += gridDim.x * blockDim.x) {
        float mv;
        if (mode == 2)      mv = (((const float*)maskp)[i] != 0.f) ? 1.f : 0.f;
        else if (mode == 1) mv = (((const unsigned char*)maskp)[i] != 0) ? 1.f : 0.f;
        else                mv = (((const int*)maskp)[i] != 0) ? 1.f : 0.f;
        if (mv != 0.f) {
            float y = lab[i];
            float x = fused[i];
            s_main += fmaxf(x, 0.f) - x * y + log1pf(__expf(-fabsf(x)));
            x = vlg[i];
            s_v0 += fmaxf(x, 0.f) - x * y + log1pf(__expf(-fabsf(x)));
            x = vlg[NN + i];
            s_v1 += fmaxf(x, 0.f) - x * y + log1pf(__expf(-fabsf(x)));
            x = vlg[2 * NN + i];
            s_v2 += fmaxf(x, 0.f) - x * y + log1pf(__expf(-fabsf(x)));
            s_cnt += 1.f;
        }
    }
    float r;
    r = blk_reduce(s_main, sm); if (threadIdx.x == 0) g_bce_part[blockIdx.x][0] = r;
    r = blk_reduce(s_v0, sm);   if (threadIdx.x == 0) g_bce_part[blockIdx.x][1] = r;
    r = blk_reduce(s_v1, sm);   if (threadIdx.x == 0) g_bce_part[blockIdx.x][2] = r;
    r = blk_reduce(s_v2, sm);   if (threadIdx.x == 0) g_bce_part[blockIdx.x][3] = r;
    r = blk_reduce(s_cnt, sm);  if (threadIdx.x == 0) g_bce_part[blockIdx.x][4] = r;
}

// ---------------- gather: build zf (sup) and zn (unsup, renormalized) ----------------
__global__ void __launch_bounds__(256) gather_kernel(const float* __restrict__ proj,
                                                     const int* __restrict__ pos,
                                                     const int* __restrict__ neg,
                                                     const int* __restrict__ unl) {
    int gw = (blockIdx.x * blockDim.x + threadIdx.x) >> 5;   // global warp id
    int lane = threadIdx.x & 31;
    if (gw >= 2 * MM) return;
    int mat = (gw >= MM) ? 1 : 0;
    int row = gw - mat * MM;
    int l = row / 3, v = row % 3;
    int idx;
    if (mat == 0) idx = (l < PP) ? pos[l] : neg[l - PP];
    else          idx = unl[l];
    const float4* src = (const float4*)(proj + ((size_t)v * NN + (size_t)idx) * DD);
    float4 x0 = src[lane];
    float4 x1 = src[lane + 32];
    if (mat == 0) {
        g_zv[0][row][lane]      = x0;
        g_zv[0][row][lane + 32] = x1;
    } else {
        float ss = x0.x * x0.x + x0.y * x0.y + x0.z * x0.z + x0.w * x0.w
                 + x1.x * x1.x + x1.y * x1.y + x1.z * x1.z + x1.w * x1.w;
#pragma unroll
        for (int o = 16; o > 0; o >>= 1) ss += __shfl_xor_sync(0xffffffffu, ss, o);
        float inv = 1.f / (sqrtf(ss) + 1e-8f);
        x0.x *= inv; x0.y *= inv; x0.z *= inv; x0.w *= inv;
        x1.x *= inv; x1.y *= inv; x1.z *= inv; x1.w *= inv;
        g_zv[1][row][lane]      = x0;
        g_zv[1][row][lane + 32] = x1;
    }
}

// ---------------- similarity GEMM + row reductions ----------------
// grid (48, NSPLIT, 2); z: 0=sup (exp(5d-5), t=sum dot over same-label), 1=unsup (exp(5d))
__global__ void __launch_bounds__(256) sim_kernel() {
    __shared__ float As[KC][PAD];
    __shared__ float Bs[KC][PAD];
    __shared__ float red[TI][16];

    int mat = blockIdx.z;
    const float* Z = (const float*)g_zv[mat];
    int I0 = blockIdx.x * TI;
    int J0base = blockIdx.y * JCHUNK;
    int tid = threadIdx.x, tx = tid & 15, ty = tid >> 4;
    bool isup = (mat == 0);
    bool rowlab = (I0 < LABSPLIT);
    float OFF = isup ? 5.f : 0.f;

    float rs[8], rt[8];
#pragma unroll
    for (int i = 0; i < 8; i++) { rs[i] = 0.f; rt[i] = 0.f; }

    int lrow = tid & 31;
    int k4 = (tid >> 5) * 4;

    for (int jt = 0; jt < JCHUNK / TJ; jt++) {
        int J0 = J0base + jt * TJ;
        unsigned long long acc[4][8];
#pragma unroll
        for (int a = 0; a < 4; a++)
#pragma unroll
            for (int b = 0; b < 8; b++) acc[a][b] = 0ull;

        for (int kk = 0; kk < DD; kk += KC) {
            __syncthreads();
#pragma unroll
            for (int rr = 0; rr < 4; rr++) {
                int row = lrow + rr * 32;
                float4 va = *(const float4*)(Z + (size_t)(I0 + row) * DD + kk + k4);
                As[k4 + 0][row] = va.x; As[k4 + 1][row] = va.y;
                As[k4 + 2][row] = va.z; As[k4 + 3][row] = va.w;
                float4 vb = *(const float4*)(Z + (size_t)(J0 + row) * DD + kk + k4);
                Bs[k4 + 0][row] = vb.x; Bs[k4 + 1][row] = vb.y;
                Bs[k4 + 2][row] = vb.z; Bs[k4 + 3][row] = vb.w;
            }
            __syncthreads();
#pragma unroll
            for (int k = 0; k < KC; k++) {
                float4 a0 = *(const float4*)&As[k][ty * 8];
                float4 a1 = *(const float4*)&As[k][ty * 8 + 4];
                float4 b0 = *(const float4*)&Bs[k][tx * 8];
                float4 b1 = *(const float4*)&Bs[k][tx * 8 + 4];
                unsigned long long ap[4];
                ap[0] = pk2(a0.x, a0.y); ap[1] = pk2(a0.z, a0.w);
                ap[2] = pk2(a1.x, a1.y); ap[3] = pk2(a1.z, a1.w);
                float bv[8] = {b0.x, b0.y, b0.z, b0.w, b1.x, b1.y, b1.z, b1.w};
#pragma unroll
                for (int j = 0; j < 8; j++) {
                    unsigned long long bd = pk2(bv[j], bv[j]);
#pragma unroll
                    for (int i2 = 0; i2 < 4; i2++)
                        acc[i2][j] = ffma2(ap[i2], bd, acc[i2][j]);
                }
            }
        }
        // epilogue for this 128x128 tile
        bool tm = isup && (rowlab == (J0 < LABSPLIT));
#pragma unroll
        for (int i2 = 0; i2 < 4; i2++) {
#pragma unroll
            for (int j = 0; j < 8; j++) {
                float lo, hi;
                upk2(acc[i2][j], lo, hi);
                rs[2 * i2]     += __expf(5.f * lo - OFF);
                rs[2 * i2 + 1] += __expf(5.f * hi - OFF);
                if (tm) { rt[2 * i2] += lo; rt[2 * i2 + 1] += hi; }
            }
        }
    }

    // reduce per-row partials across the 16 tx threads
    __syncthreads();
#pragma unroll
    for (int i = 0; i < 8; i++) red[ty * 8 + i][tx] = rs[i];
    __syncthreads();
    if (tid < TI) {
        float s = 0.f;
#pragma unroll
        for (int x = 0; x < 16; x++) s += red[tid][x];
        g_s[mat][blockIdx.y][I0 + tid] = s;
    }
    __syncthreads();
    if (isup) {
#pragma unroll
        for (int i = 0; i < 8; i++) red[ty * 8 + i][tx] = rt[i];
        __syncthreads();
        if (tid < TI) {
            float s = 0.f;
#pragma unroll
            for (int x = 0; x < 16; x++) s += red[tid][x];
            g_t[blockIdx.y][I0 + tid] = s;
        }
    }
}

// ---------------- sup finalize: per-row loss ----------------
// loss_i = log(sum_{j != i} exp(sim - 5)) + 5 - p_i / 3071,  p_i = 5*(t_i - 1)
__global__ void __launch_bounds__(256) supfin_kernel() {
    __shared__ float sm[256];
    int row = blockIdx.x * 256 + threadIdx.x;  // grid 24 -> 6144 rows
    float s = g_s[0][0][row] + g_s[0][1][row] + g_s[0][2][row];
    float t = g_t[0][row] + g_t[1][row] + g_t[2][row];
    float denom = s - 1.0f + 1e-12f;           // remove diagonal exp(0)=1
    float loss = logf(denom) + 5.0f - (5.0f * t - 5.0f) / 3071.0f;
    float r = blk_reduce(loss, sm);
    if (threadIdx.x == 0) g_sup_part[blockIdx.x] = r;
}

// ---------------- unsup finalize: per-node (3 anchors) ----------------
__global__ void __launch_bounds__(256) unfin_kernel() {
    __shared__ float sm[256];
    int gw = (blockIdx.x * 256 + threadIdx.x) >> 5;  // 2048 warps
    int lane = threadIdx.x & 31;
    float acc = 0.f;
    if (gw < UU) {
        int u = gw;
        const float4* r0 = g_zv[1][3 * u + 0];
        const float4* r1 = g_zv[1][3 * u + 1];
        const float4* r2 = g_zv[1][3 * u + 2];
        float4 a0 = r0[lane], a1 = r0[lane + 32];
        float4 b0 = r1[lane], b1 = r1[lane + 32];
        float4 c0 = r2[lane], c1 = r2[lane + 32];
        float d01 = a0.x * b0.x + a0.y * b0.y + a0.z * b0.z + a0.w * b0.w
                  + a1.x * b1.x + a1.y * b1.y + a1.z * b1.z + a1.w * b1.w;
        float d02 = a0.x * c0.x + a0.y * c0.y + a0.z * c0.z + a0.w * c0.w
                  + a1.x * c1.x + a1.y * c1.y + a1.z * c1.z + a1.w * c1.w;
        float d12 = b0.x * c0.x + b0.y * c0.y + b0.z * c0.z + b0.w * c0.w
                  + b1.x * c1.x + b1.y * c1.y + b1.z * c1.z + b1.w * c1.w;
#pragma unroll
        for (int o = 16; o > 0; o >>= 1) {
            d01 += __shfl_xor_sync(0xffffffffu, d01, o);
            d02 += __shfl_xor_sync(0xffffffffu, d02, o);
            d12 += __shfl_xor_sync(0xffffffffu, d12, o);
        }
        if (lane == 0) {
            float e5 = __expf(5.0f);
            float s0 = g_s[1][0][3 * u + 0] + g_s[1][1][3 * u + 0] + g_s[1][2][3 * u + 0];
            float s1 = g_s[1][0][3 * u + 1] + g_s[1][1][3 * u + 1] + g_s[1][2][3 * u + 1];
            float s2 = g_s[1][0][3 * u + 2] + g_s[1][1][3 * u + 2] + g_s[1][2][3 * u + 2];
            float per0 = logf(s0 - e5 + 1e-12f) - 2.5f * (d01 + d02);
            float per1 = logf(s1 - e5 + 1e-12f) - 2.5f * (d01 + d12);
            float per2 = logf(s2 - e5 + 1e-12f) - 2.5f * (d02 + d12);
            acc = per0 + per1 + per2;
        }
    }
    float r = blk_reduce(acc, sm);
    if (threadIdx.x == 0) g_un_part[blockIdx.x] = r;
}

// ---------------- final merge ----------------
__global__ void __launch_bounds__(256) final_kernel(float* __restrict__ out) {
    __shared__ float sm[256];
    int tid = threadIdx.x;
    float c0 = blk_reduce((tid < BCE_BLOCKS) ? g_bce_part[tid][0] : 0.f, sm);
    float c1 = blk_reduce((tid < BCE_BLOCKS) ? g_bce_part[tid][1] : 0.f, sm);
    float c2 = blk_reduce((tid < BCE_BLOCKS) ? g_bce_part[tid][2] : 0.f, sm);
    float c3 = blk_reduce((tid < BCE_BLOCKS) ? g_bce_part[tid][3] : 0.f, sm);
    float cnt = blk_reduce((tid < BCE_BLOCKS) ? g_bce_part[tid][4] : 0.f, sm);
    float sup_sum = blk_reduce((tid < 24) ? g_sup_part[tid] : 0.f, sm);
    float un_sum = blk_reduce(g_un_part[tid], sm);
    if (tid == 0) {
        float denom = fmaxf(cnt, 1.0f);
        float main_loss = c0 / denom;
        float view_loss = (c1 + c2 + c3) / (3.0f * denom);
        float sup_loss = sup_sum / (float)MM;
        float un_loss = un_sum / (float)MM;
        float total = main_loss + view_loss + sup_loss + 0.2f * un_loss;
        out[0] = total;
        out[1] = main_loss;
        out[2] = view_loss;
        out[3] = sup_loss;
        out[4] = un_loss;
    }
}

// ---------------- launch ----------------
extern "C" void kernel_launch(void* const* d_in, const int* in_sizes, int n_in,
                              void* d_out, int out_size) {
    const float* fused = (const float*)d_in[0];
    const float* vlg   = (const float*)d_in[1];
    const float* proj  = (const float*)d_in[2];
    const float* lab   = (const float*)d_in[3];
    const void*  maskp = d_in[4];
    const int*   pos   = (const int*)d_in[5];
    const int*   neg   = (const int*)d_in[6];
    const int*   unl   = (const int*)d_in[7];
    float* out = (float*)d_out;
    int n = in_sizes[0];

    detect_mask_kernel<<<1, 32>>>((const unsigned char*)maskp);
    bce_kernel<<<BCE_BLOCKS, 256>>>(fused, vlg, lab, maskp, n);
    gather_kernel<<<(2 * MM * 32) / 256, 256>>>(proj, pos, neg, unl);
    sim_kernel<<<dim3(MM / TI, NSPLIT, 2), 256>>>();
    supfin_kernel<<<MM / 256, 256>>>();
    unfin_kernel<<<(UU * 32) / 256, 256>>>();
    final_kernel<<<1, 256>>>(out);
}

// round 4
// speedup vs baseline: 2.6091x; 2.6091x over previous
#include <cuda_runtime.h>
#include <cuda_bf16.h>
#include <stdint.h>

// ---------------- problem constants ----------------
#define NN      100000
#define DD      256
#define PP      1024
#define UU      2048
#define MM      6144          // rows per similarity matrix (2048*3)
#define BLK     48            // 6144/128 row blocks
#define NTILE   1176          // 48*49/2 upper-tri tiles
#define BCE_BLOCKS 128

#define PITCH   144           // padded smem row bytes (64 bf16 -> 128B + 16 pad)
#define STAGE_OP (128 * PITCH)        // 18432 bytes per operand
#define STAGE_SZ (2 * STAGE_OP)       // 36864 per stage (A+B)
#define SMEM_DYN (2 * STAGE_SZ)       // 73728 double buffered

// ---------------- device scratch ----------------
__device__ __align__(16) __nv_bfloat16 g_hl[2][2][MM][DD]; // [mat][h/l][row][col]
__device__ float4 g_zn[MM][64];                 // unsup renormalized fp32 rows
__device__ float  g_spart[2][BLK][MM];          // per-(otherblock,row) sum of exp
__device__ float  g_tpart[BLK][MM];             // per-(otherblock,row) sum of dot (sup)
__device__ float  g_bce_part[BCE_BLOCKS][5];
__device__ float  g_sup_part[24];
__device__ float  g_un_part[256];
__device__ int    g_maskmode;

// ---------------- helpers ----------------
__device__ __forceinline__ uint32_t smem_u32(const void* p) {
    uint32_t a;
    asm("{ .reg .u64 t; cvta.to.shared.u64 t, %1; cvt.u32.u64 %0, t; }" : "=r"(a) : "l"(p));
    return a;
}

__device__ __forceinline__ float blk_reduce(float v, float* sm) {
    int tid = threadIdx.x;
    sm[tid] = v; __syncthreads();
#pragma unroll
    for (int s = 128; s > 0; s >>= 1) {
        if (tid < s) sm[tid] += sm[tid + s];
        __syncthreads();
    }
    float r = sm[0]; __syncthreads();
    return r;
}

// ---------------- mask dtype detection ----------------
__global__ void detect_mask_kernel(const unsigned char* m) {
    if (threadIdx.x == 0 && blockIdx.x == 0) {
        bool nonbin = false, oddone = false;
        for (int i = 0; i < 256; i++) {
            unsigned char b = m[i];
            if (b > 1) nonbin = true;
            else if (b == 1 && (i & 3)) oddone = true;
        }
        g_maskmode = nonbin ? 2 : (oddone ? 1 : 0);
    }
}

// ---------------- BCE partial sums ----------------
__global__ void __launch_bounds__(256) bce_kernel(const float* __restrict__ fused,
                                                  const float* __restrict__ vlg,
                                                  const float* __restrict__ lab,
                                                  const void* __restrict__ maskp,
                                                  int n) {
    __shared__ float sm[256];
    int mode = g_maskmode;
    float s_main = 0.f, s_v0 = 0.f, s_v1 = 0.f, s_v2 = 0.f, s_cnt = 0.f;
    for (int i = blockIdx.x * blockDim.x + threadIdx.x; i < n; i += gridDim.x * blockDim.x) {
        float mv;
        if (mode == 2)      mv = (((const float*)maskp)[i] != 0.f) ? 1.f : 0.f;
        else if (mode == 1) mv = (((const unsigned char*)maskp)[i] != 0) ? 1.f : 0.f;
        else                mv = (((const int*)maskp)[i] != 0) ? 1.f : 0.f;
        if (mv != 0.f) {
            float y = lab[i];
            float x = fused[i];
            s_main += fmaxf(x, 0.f) - x * y + log1pf(__expf(-fabsf(x)));
            x = vlg[i];
            s_v0 += fmaxf(x, 0.f) - x * y + log1pf(__expf(-fabsf(x)));
            x = vlg[NN + i];
            s_v1 += fmaxf(x, 0.f) - x * y + log1pf(__expf(-fabsf(x)));
            x = vlg[2 * NN + i];
            s_v2 += fmaxf(x, 0.f) - x * y + log1pf(__expf(-fabsf(x)));
            s_cnt += 1.f;
        }
    }
    float r;
    r = blk_reduce(s_main, sm); if (threadIdx.x == 0) g_bce_part[blockIdx.x][0] = r;
    r = blk_reduce(s_v0, sm);   if (threadIdx.x == 0) g_bce_part[blockIdx.x][1] = r;
    r = blk_reduce(s_v1, sm);   if (threadIdx.x == 0) g_bce_part[blockIdx.x][2] = r;
    r = blk_reduce(s_v2, sm);   if (threadIdx.x == 0) g_bce_part[blockIdx.x][3] = r;
    r = blk_reduce(s_cnt, sm);  if (threadIdx.x == 0) g_bce_part[blockIdx.x][4] = r;
}

// ---------------- gather: bf16 h/l split rows ----------------
__device__ __forceinline__ void store_hl(int mat, int row, int k0, float4 v) {
    __nv_bfloat16 h0 = __float2bfloat16(v.x), h1 = __float2bfloat16(v.y);
    __nv_bfloat16 h2 = __float2bfloat16(v.z), h3 = __float2bfloat16(v.w);
    __nv_bfloat16 l0 = __float2bfloat16(v.x - __bfloat162float(h0));
    __nv_bfloat16 l1 = __float2bfloat16(v.y - __bfloat162float(h1));
    __nv_bfloat16 l2 = __float2bfloat16(v.z - __bfloat162float(h2));
    __nv_bfloat16 l3 = __float2bfloat16(v.w - __bfloat162float(h3));
    uint2 hp, lp;
    hp.x = (uint32_t)__bfloat16_as_ushort(h0) | ((uint32_t)__bfloat16_as_ushort(h1) << 16);
    hp.y = (uint32_t)__bfloat16_as_ushort(h2) | ((uint32_t)__bfloat16_as_ushort(h3) << 16);
    lp.x = (uint32_t)__bfloat16_as_ushort(l0) | ((uint32_t)__bfloat16_as_ushort(l1) << 16);
    lp.y = (uint32_t)__bfloat16_as_ushort(l2) | ((uint32_t)__bfloat16_as_ushort(l3) << 16);
    *(uint2*)&g_hl[mat][0][row][k0] = hp;
    *(uint2*)&g_hl[mat][1][row][k0] = lp;
}

__global__ void __launch_bounds__(256) gather_kernel(const float* __restrict__ proj,
                                                     const int* __restrict__ pos,
                                                     const int* __restrict__ neg,
                                                     const int* __restrict__ unl) {
    int gw = (blockIdx.x * blockDim.x + threadIdx.x) >> 5;
    int lane = threadIdx.x & 31;
    if (gw >= 2 * MM) return;
    int mat = (gw >= MM) ? 1 : 0;
    int row = gw - mat * MM;
    int l = row / 3, v = row % 3;
    int idx;
    if (mat == 0) idx = (l < PP) ? pos[l] : neg[l - PP];
    else          idx = unl[l];
    const float4* src = (const float4*)(proj + ((size_t)v * NN + (size_t)idx) * DD);
    float4 x0 = src[lane];
    float4 x1 = src[lane + 32];
    if (mat == 1) {
        float ss = x0.x * x0.x + x0.y * x0.y + x0.z * x0.z + x0.w * x0.w
                 + x1.x * x1.x + x1.y * x1.y + x1.z * x1.z + x1.w * x1.w;
#pragma unroll
        for (int o = 16; o > 0; o >>= 1) ss += __shfl_xor_sync(0xffffffffu, ss, o);
        float inv = 1.f / (sqrtf(ss) + 1e-8f);
        x0.x *= inv; x0.y *= inv; x0.z *= inv; x0.w *= inv;
        x1.x *= inv; x1.y *= inv; x1.z *= inv; x1.w *= inv;
        g_zn[row][lane]      = x0;
        g_zn[row][lane + 32] = x1;
    }
    store_hl(mat, row, 4 * lane, x0);
    store_hl(mat, row, 128 + 4 * lane, x1);
}

// ---------------- HMMA similarity kernel (upper-triangular tiles) ----------------
// FIXED: 8 transfers per thread (2048 total) to cover both full 128x128B operands.
__device__ __forceinline__ void load_chunk(uint32_t sbase, int buf, int m, int I, int J,
                                           int chunk, int tid) {
    int q = chunk >> 2;             // split term: 0=h*h 1=h*l 2=l*h
    int kk = (chunk & 3) * 64;
    const __nv_bfloat16* Asrc = &g_hl[m][(q == 2) ? 1 : 0][I * 128][0];
    const __nv_bfloat16* Bsrc = &g_hl[m][(q == 1) ? 1 : 0][J * 128][0];
    uint32_t base = sbase + buf * STAGE_SZ;
#pragma unroll
    for (int i = 0; i < 8; i++) {
        int idx = tid * 8 + i;
        int op = idx >> 10, rc = idx & 1023, row = rc >> 3, c16 = rc & 7;
        const __nv_bfloat16* src = (op ? Bsrc : Asrc) + row * DD + kk + c16 * 8;
        uint32_t dst = base + op * STAGE_OP + row * PITCH + c16 * 16;
        asm volatile("cp.async.cg.shared.global [%0], [%1], 16;" :: "r"(dst), "l"(src));
    }
    asm volatile("cp.async.commit_group;" ::: "memory");
}

__global__ void __launch_bounds__(256, 1) simmma_kernel() {
    extern __shared__ __align__(16) unsigned char smem[];
    const int tid = threadIdx.x, lane = tid & 31, wid = tid >> 5;
    const int wm = wid >> 2, wn = wid & 3;     // warp tile: rows wm*64.., cols wn*32..
    const int m = blockIdx.y;
    int t = blockIdx.x, I = 0;
    while (t >= BLK - I) { t -= BLK - I; I++; }
    const int J = I + t;
    uint32_t sbase = smem_u32(smem);

    float C[4][4][4];
#pragma unroll
    for (int a = 0; a < 4; a++)
#pragma unroll
        for (int b = 0; b < 4; b++)
#pragma unroll
            for (int c = 0; c < 4; c++) C[a][b][c] = 0.f;

    load_chunk(sbase, 0, m, I, J, 0, tid);
    for (int c = 0; c < 12; c++) {
        int buf = c & 1;
        if (c + 1 < 12) {
            load_chunk(sbase, buf ^ 1, m, I, J, c + 1, tid);
            asm volatile("cp.async.wait_group 1;" ::: "memory");
        } else {
            asm volatile("cp.async.wait_group 0;" ::: "memory");
        }
        __syncthreads();
        uint32_t Abase = sbase + buf * STAGE_SZ;
        uint32_t Bbase = Abase + STAGE_OP;
#pragma unroll
        for (int ks = 0; ks < 4; ks++) {
            uint32_t a[4][4], b[2][4];
#pragma unroll
            for (int mi = 0; mi < 4; mi++) {
                uint32_t addr = Abase + (wm * 64 + mi * 16 + (lane & 15)) * PITCH
                              + (ks * 16 + (lane >> 4) * 8) * 2;
                asm volatile("ldmatrix.sync.aligned.m8n8.x4.shared.b16 {%0,%1,%2,%3}, [%4];"
                    : "=r"(a[mi][0]), "=r"(a[mi][1]), "=r"(a[mi][2]), "=r"(a[mi][3]) : "r"(addr));
            }
#pragma unroll
            for (int nP = 0; nP < 2; nP++) {
                int g = lane >> 3;
                uint32_t addr = Bbase + (wn * 32 + (nP * 2 + (g >> 1)) * 8 + (lane & 7)) * PITCH
                              + (ks * 16 + (g & 1) * 8) * 2;
                asm volatile("ldmatrix.sync.aligned.m8n8.x4.shared.b16 {%0,%1,%2,%3}, [%4];"
                    : "=r"(b[nP][0]), "=r"(b[nP][1]), "=r"(b[nP][2]), "=r"(b[nP][3]) : "r"(addr));
            }
#pragma unroll
            for (int mi = 0; mi < 4; mi++)
#pragma unroll
                for (int ni = 0; ni < 4; ni++) {
                    uint32_t b0 = b[ni >> 1][(ni & 1) * 2];
                    uint32_t b1 = b[ni >> 1][(ni & 1) * 2 + 1];
                    asm volatile(
                        "mma.sync.aligned.m16n8k16.row.col.f32.bf16.bf16.f32 "
                        "{%0,%1,%2,%3}, {%4,%5,%6,%7}, {%8,%9}, {%0,%1,%2,%3};"
                        : "+f"(C[mi][ni][0]), "+f"(C[mi][ni][1]),
                          "+f"(C[mi][ni][2]), "+f"(C[mi][ni][3])
                        : "r"(a[mi][0]), "r"(a[mi][1]), "r"(a[mi][2]), "r"(a[mi][3]),
                          "r"(b0), "r"(b1));
                }
        }
        __syncthreads();
    }

    // ---------- epilogue: row/col exp & raw sums (registers -> smem -> gmem) ----------
    const float OFF = (m == 0) ? 5.f : 0.f;
    const bool lm = (I < 24) == (J < 24);
    float rE[8], rR[8], cE[8], cR[8];
#pragma unroll
    for (int k = 0; k < 8; k++) { rE[k] = rR[k] = cE[k] = cR[k] = 0.f; }
#pragma unroll
    for (int mi = 0; mi < 4; mi++)
#pragma unroll
        for (int ni = 0; ni < 4; ni++)
#pragma unroll
            for (int f = 0; f < 4; f++) {
                int half = f >> 1, j = f & 1;
                float v = C[mi][ni][f];
                float e = __expf(5.f * v - OFF);
                rE[mi * 2 + half] += e; rR[mi * 2 + half] += v;
                cE[ni * 2 + j]    += e; cR[ni * 2 + j]    += v;
            }

    float* scRowE = (float*)smem;          // [128][4]
    float* scRowR = scRowE + 512;          // [128][4]
    float* scColE = scRowR + 512;          // [128][2]
    float* scColR = scColE + 256;          // [128][2]
#pragma unroll
    for (int k = 0; k < 8; k++) {
        float vE = rE[k], vR = rR[k];
        vE += __shfl_xor_sync(0xffffffffu, vE, 1);
        vE += __shfl_xor_sync(0xffffffffu, vE, 2);
        vR += __shfl_xor_sync(0xffffffffu, vR, 1);
        vR += __shfl_xor_sync(0xffffffffu, vR, 2);
        if ((lane & 3) == 0) {
            int r = wm * 64 + (k >> 1) * 16 + (k & 1) * 8 + (lane >> 2);
            scRowE[r * 4 + wn] = vE;
            scRowR[r * 4 + wn] = vR;
        }
    }
#pragma unroll
    for (int k = 0; k < 8; k++) {
        float vE = cE[k], vR = cR[k];
        vE += __shfl_xor_sync(0xffffffffu, vE, 4);
        vE += __shfl_xor_sync(0xffffffffu, vE, 8);
        vE += __shfl_xor_sync(0xffffffffu, vE, 16);
        vR += __shfl_xor_sync(0xffffffffu, vR, 4);
        vR += __shfl_xor_sync(0xffffffffu, vR, 8);
        vR += __shfl_xor_sync(0xffffffffu, vR, 16);
        if (lane < 4) {
            int cc = wn * 32 + (k >> 1) * 8 + (lane & 3) * 2 + (k & 1);
            scColE[cc * 2 + wm] = vE;
            scColR[cc * 2 + wm] = vR;
        }
    }
    __syncthreads();
    if (tid < 128) {
        int r = tid;
        float sE = scRowE[r * 4] + scRowE[r * 4 + 1] + scRowE[r * 4 + 2] + scRowE[r * 4 + 3];
        float sR = scRowR[r * 4] + scRowR[r * 4 + 1] + scRowR[r * 4 + 2] + scRowR[r * 4 + 3];
        g_spart[m][J][I * 128 + r] = sE;
        if (m == 0) g_tpart[J][I * 128 + r] = lm ? sR : 0.f;
    } else if (I != J) {
        int cc = tid - 128;
        float sE = scColE[cc * 2] + scColE[cc * 2 + 1];
        float sR = scColR[cc * 2] + scColR[cc * 2 + 1];
        g_spart[m][I][J * 128 + cc] = sE;
        if (m == 0) g_tpart[I][J * 128 + cc] = lm ? sR : 0.f;
    }
}

// ---------------- sup finalize ----------------
__global__ void __launch_bounds__(256) supfin_kernel() {
    __shared__ float sm[256];
    int row = blockIdx.x * 256 + threadIdx.x;  // 24 blocks
    float s = 0.f, t = 0.f;
#pragma unroll
    for (int o = 0; o < BLK; o++) { s += g_spart[0][o][row]; t += g_tpart[o][row]; }
    float denom = s - 1.0f + 1e-12f;           // remove diagonal exp(0)=1
    float loss = logf(denom) + 5.0f - (5.0f * t - 5.0f) / 3071.0f;
    float r = blk_reduce(loss, sm);
    if (threadIdx.x == 0) g_sup_part[blockIdx.x] = r;
}

// ---------------- unsup finalize ----------------
__global__ void __launch_bounds__(256) unfin_kernel() {
    __shared__ float sm[256];
    int gw = (blockIdx.x * 256 + threadIdx.x) >> 5;  // 2048 warps
    int lane = threadIdx.x & 31;
    float acc = 0.f;
    if (gw < UU) {
        int u = gw;
        const float4* r0 = g_zn[3 * u + 0];
        const float4* r1 = g_zn[3 * u + 1];
        const float4* r2 = g_zn[3 * u + 2];
        float4 a0 = r0[lane], a1 = r0[lane + 32];
        float4 b0 = r1[lane], b1 = r1[lane + 32];
        float4 c0 = r2[lane], c1 = r2[lane + 32];
        float d01 = a0.x * b0.x + a0.y * b0.y + a0.z * b0.z + a0.w * b0.w
                  + a1.x * b1.x + a1.y * b1.y + a1.z * b1.z + a1.w * b1.w;
        float d02 = a0.x * c0.x + a0.y * c0.y + a0.z * c0.z + a0.w * c0.w
                  + a1.x * c1.x + a1.y * c1.y + a1.z * c1.z + a1.w * c1.w;
        float d12 = b0.x * c0.x + b0.y * c0.y + b0.z * c0.z + b0.w * c0.w
                  + b1.x * c1.x + b1.y * c1.y + b1.z * c1.z + b1.w * c1.w;
#pragma unroll
        for (int o = 16; o > 0; o >>= 1) {
            d01 += __shfl_xor_sync(0xffffffffu, d01, o);
            d02 += __shfl_xor_sync(0xffffffffu, d02, o);
            d12 += __shfl_xor_sync(0xffffffffu, d12, o);
        }
        if (lane == 0) {
            float e5 = __expf(5.0f);
            float s0 = 0.f, s1 = 0.f, s2 = 0.f;
#pragma unroll
            for (int o = 0; o < BLK; o++) {
                s0 += g_spart[1][o][3 * u + 0];
                s1 += g_spart[1][o][3 * u + 1];
                s2 += g_spart[1][o][3 * u + 2];
            }
            float per0 = logf(s0 - e5 + 1e-12f) - 2.5f * (d01 + d02);
            float per1 = logf(s1 - e5 + 1e-12f) - 2.5f * (d01 + d12);
            float per2 = logf(s2 - e5 + 1e-12f) - 2.5f * (d02 + d12);
            acc = per0 + per1 + per2;
        }
    }
    float r = blk_reduce(acc, sm);
    if (threadIdx.x == 0) g_un_part[blockIdx.x] = r;
}

// ---------------- final merge ----------------
__global__ void __launch_bounds__(256) final_kernel(float* __restrict__ out) {
    __shared__ float sm[256];
    int tid = threadIdx.x;
    float c0 = blk_reduce((tid < BCE_BLOCKS) ? g_bce_part[tid][0] : 0.f, sm);
    float c1 = blk_reduce((tid < BCE_BLOCKS) ? g_bce_part[tid][1] : 0.f, sm);
    float c2 = blk_reduce((tid < BCE_BLOCKS) ? g_bce_part[tid][2] : 0.f, sm);
    float c3 = blk_reduce((tid < BCE_BLOCKS) ? g_bce_part[tid][3] : 0.f, sm);
    float cnt = blk_reduce((tid < BCE_BLOCKS) ? g_bce_part[tid][4] : 0.f, sm);
    float sup_sum = blk_reduce((tid < 24) ? g_sup_part[tid] : 0.f, sm);
    float un_sum = blk_reduce(g_un_part[tid], sm);
    if (tid == 0) {
        float denom = fmaxf(cnt, 1.0f);
        float main_loss = c0 / denom;
        float view_loss = (c1 + c2 + c3) / (3.0f * denom);
        float sup_loss = sup_sum / (float)MM;
        float un_loss = un_sum / (float)MM;
        float total = main_loss + view_loss + sup_loss + 0.2f * un_loss;
        out[0] = total;
        out[1] = main_loss;
        out[2] = view_loss;
        out[3] = sup_loss;
        out[4] = un_loss;
    }
}

// ---------------- launch ----------------
extern "C" void kernel_launch(void* const* d_in, const int* in_sizes, int n_in,
                              void* d_out, int out_size) {
    const float* fused = (const float*)d_in[0];
    const float* vlg   = (const float*)d_in[1];
    const float* proj  = (const float*)d_in[2];
    const float* lab   = (const float*)d_in[3];
    const void*  maskp = d_in[4];
    const int*   pos   = (const int*)d_in[5];
    const int*   neg   = (const int*)d_in[6];
    const int*   unl   = (const int*)d_in[7];
    float* out = (float*)d_out;
    int n = in_sizes[0];

    cudaFuncSetAttribute(simmma_kernel, cudaFuncAttributeMaxDynamicSharedMemorySize, SMEM_DYN);

    detect_mask_kernel<<<1, 32>>>((const unsigned char*)maskp);
    bce_kernel<<<BCE_BLOCKS, 256>>>(fused, vlg, lab, maskp, n);
    gather_kernel<<<(2 * MM * 32) / 256, 256>>>(proj, pos, neg, unl);
    simmma_kernel<<<dim3(NTILE, 2), 256, SMEM_DYN>>>();
    supfin_kernel<<<MM / 256, 256>>>();
    unfin_kernel<<<(UU * 32) / 256, 256>>>();
    final_kernel<<<1, 256>>>(out);
}

// round 5
// speedup vs baseline: 3.1125x; 1.1929x over previous
#include <cuda_runtime.h>
#include <cuda_bf16.h>
#include <stdint.h>

// ---------------- problem constants ----------------
#define NN      100000
#define DD      256
#define PP      1024
#define UU      2048
#define MM      6144          // rows per similarity matrix (2048*3)
#define BLK     48            // 6144/128 row blocks
#define NTILE   1176          // 48*49/2 upper-tri tiles
#define BCE_BLOCKS 128

#define PITCH   144           // padded smem row bytes (64 bf16 -> 128B + 16 pad)
#define STAGE_OP (128 * PITCH)        // 18432 bytes per operand
#define STAGE_SZ (2 * STAGE_OP)       // 36864 per stage (A+B)
#define NSTAGE  3
#define SMEM_DYN (NSTAGE * STAGE_SZ)  // 110592, 3-deep pipeline

// ---------------- device scratch ----------------
__device__ __align__(16) __nv_bfloat16 g_hl[2][2][MM][DD]; // [mat][h/l][row][col]
__device__ float4 g_zn[MM][64];                 // unsup renormalized fp32 rows
__device__ float  g_spart[2][BLK][MM];          // per-(otherblock,row) sum of exp
__device__ float  g_tpart[BLK][MM];             // per-(otherblock,row) sum of dot (sup)
__device__ float  g_bce_part[BCE_BLOCKS][5];
__device__ float  g_sup_part[24];
__device__ float  g_un_part[256];
__device__ int    g_maskmode;

// ---------------- helpers ----------------
__device__ __forceinline__ uint32_t smem_u32(const void* p) {
    uint32_t a;
    asm("{ .reg .u64 t; cvta.to.shared.u64 t, %1; cvt.u32.u64 %0, t; }" : "=r"(a) : "l"(p));
    return a;
}

__device__ __forceinline__ float blk_reduce(float v, float* sm) {
    int tid = threadIdx.x;
    sm[tid] = v; __syncthreads();
#pragma unroll
    for (int s = 128; s > 0; s >>= 1) {
        if (tid < s) sm[tid] += sm[tid + s];
        __syncthreads();
    }
    float r = sm[0]; __syncthreads();
    return r;
}

// ---------------- mask dtype detection ----------------
__global__ void detect_mask_kernel(const unsigned char* m) {
    if (threadIdx.x == 0 && blockIdx.x == 0) {
        bool nonbin = false, oddone = false;
        for (int i = 0; i < 256; i++) {
            unsigned char b = m[i];
            if (b > 1) nonbin = true;
            else if (b == 1 && (i & 3)) oddone = true;
        }
        g_maskmode = nonbin ? 2 : (oddone ? 1 : 0);
    }
}

// ---------------- BCE partial sums ----------------
__global__ void __launch_bounds__(256) bce_kernel(const float* __restrict__ fused,
                                                  const float* __restrict__ vlg,
                                                  const float* __restrict__ lab,
                                                  const void* __restrict__ maskp,
                                                  int n) {
    __shared__ float sm[256];
    int mode = g_maskmode;
    float s_main = 0.f, s_v0 = 0.f, s_v1 = 0.f, s_v2 = 0.f, s_cnt = 0.f;
    for (int i = blockIdx.x * blockDim.x + threadIdx.x; i < n; i += gridDim.x * blockDim.x) {
        float mv;
        if (mode == 2)      mv = (((const float*)maskp)[i] != 0.f) ? 1.f : 0.f;
        else if (mode == 1) mv = (((const unsigned char*)maskp)[i] != 0) ? 1.f : 0.f;
        else                mv = (((const int*)maskp)[i] != 0) ? 1.f : 0.f;
        if (mv != 0.f) {
            float y = lab[i];
            float x = fused[i];
            s_main += fmaxf(x, 0.f) - x * y + log1pf(__expf(-fabsf(x)));
            x = vlg[i];
            s_v0 += fmaxf(x, 0.f) - x * y + log1pf(__expf(-fabsf(x)));
            x = vlg[NN + i];
            s_v1 += fmaxf(x, 0.f) - x * y + log1pf(__expf(-fabsf(x)));
            x = vlg[2 * NN + i];
            s_v2 += fmaxf(x, 0.f) - x * y + log1pf(__expf(-fabsf(x)));
            s_cnt += 1.f;
        }
    }
    float r;
    r = blk_reduce(s_main, sm); if (threadIdx.x == 0) g_bce_part[blockIdx.x][0] = r;
    r = blk_reduce(s_v0, sm);   if (threadIdx.x == 0) g_bce_part[blockIdx.x][1] = r;
    r = blk_reduce(s_v1, sm);   if (threadIdx.x == 0) g_bce_part[blockIdx.x][2] = r;
    r = blk_reduce(s_v2, sm);   if (threadIdx.x == 0) g_bce_part[blockIdx.x][3] = r;
    r = blk_reduce(s_cnt, sm);  if (threadIdx.x == 0) g_bce_part[blockIdx.x][4] = r;
}

// ---------------- gather: bf16 h/l split rows ----------------
__device__ __forceinline__ void store_hl(int mat, int row, int k0, float4 v) {
    __nv_bfloat16 h0 = __float2bfloat16(v.x), h1 = __float2bfloat16(v.y);
    __nv_bfloat16 h2 = __float2bfloat16(v.z), h3 = __float2bfloat16(v.w);
    __nv_bfloat16 l0 = __float2bfloat16(v.x - __bfloat162float(h0));
    __nv_bfloat16 l1 = __float2bfloat16(v.y - __bfloat162float(h1));
    __nv_bfloat16 l2 = __float2bfloat16(v.z - __bfloat162float(h2));
    __nv_bfloat16 l3 = __float2bfloat16(v.w - __bfloat162float(h3));
    uint2 hp, lp;
    hp.x = (uint32_t)__bfloat16_as_ushort(h0) | ((uint32_t)__bfloat16_as_ushort(h1) << 16);
    hp.y = (uint32_t)__bfloat16_as_ushort(h2) | ((uint32_t)__bfloat16_as_ushort(h3) << 16);
    lp.x = (uint32_t)__bfloat16_as_ushort(l0) | ((uint32_t)__bfloat16_as_ushort(l1) << 16);
    lp.y = (uint32_t)__bfloat16_as_ushort(l2) | ((uint32_t)__bfloat16_as_ushort(l3) << 16);
    *(uint2*)&g_hl[mat][0][row][k0] = hp;
    *(uint2*)&g_hl[mat][1][row][k0] = lp;
}

__global__ void __launch_bounds__(256) gather_kernel(const float* __restrict__ proj,
                                                     const int* __restrict__ pos,
                                                     const int* __restrict__ neg,
                                                     const int* __restrict__ unl) {
    int gw = (blockIdx.x * blockDim.x + threadIdx.x) >> 5;
    int lane = threadIdx.x & 31;
    if (gw >= 2 * MM) return;
    int mat = (gw >= MM) ? 1 : 0;
    int row = gw - mat * MM;
    int l = row / 3, v = row % 3;
    int idx;
    if (mat == 0) idx = (l < PP) ? pos[l] : neg[l - PP];
    else          idx = unl[l];
    const float4* src = (const float4*)(proj + ((size_t)v * NN + (size_t)idx) * DD);
    float4 x0 = src[lane];
    float4 x1 = src[lane + 32];
    if (mat == 1) {
        float ss = x0.x * x0.x + x0.y * x0.y + x0.z * x0.z + x0.w * x0.w
                 + x1.x * x1.x + x1.y * x1.y + x1.z * x1.z + x1.w * x1.w;
#pragma unroll
        for (int o = 16; o > 0; o >>= 1) ss += __shfl_xor_sync(0xffffffffu, ss, o);
        float inv = 1.f / (sqrtf(ss) + 1e-8f);
        x0.x *= inv; x0.y *= inv; x0.z *= inv; x0.w *= inv;
        x1.x *= inv; x1.y *= inv; x1.z *= inv; x1.w *= inv;
        g_zn[row][lane]      = x0;
        g_zn[row][lane + 32] = x1;
    }
    store_hl(mat, row, 4 * lane, x0);
    store_hl(mat, row, 128 + 4 * lane, x1);
}

// ---------------- HMMA similarity kernel (upper-triangular tiles) ----------------
// 512 threads: 2048 cp.async of 16B per chunk = 4 per thread.
__device__ __forceinline__ void load_chunk(uint32_t sbase, int buf, int m, int I, int J,
                                           int chunk, int tid) {
    int q = chunk >> 2;             // split term: 0=h*h 1=h*l 2=l*h
    int kk = (chunk & 3) * 64;
    const __nv_bfloat16* Asrc = &g_hl[m][(q == 2) ? 1 : 0][I * 128][0];
    const __nv_bfloat16* Bsrc = &g_hl[m][(q == 1) ? 1 : 0][J * 128][0];
    uint32_t base = sbase + buf * STAGE_SZ;
#pragma unroll
    for (int i = 0; i < 4; i++) {
        int idx = tid * 4 + i;
        int op = idx >> 10, rc = idx & 1023, row = rc >> 3, c16 = rc & 7;
        const __nv_bfloat16* src = (op ? Bsrc : Asrc) + row * DD + kk + c16 * 8;
        uint32_t dst = base + op * STAGE_OP + row * PITCH + c16 * 16;
        asm volatile("cp.async.cg.shared.global [%0], [%1], 16;" :: "r"(dst), "l"(src));
    }
    asm volatile("cp.async.commit_group;" ::: "memory");
}

__global__ void __launch_bounds__(512, 1) simmma_kernel() {
    extern __shared__ __align__(16) unsigned char smem[];
    const int tid = threadIdx.x, lane = tid & 31, wid = tid >> 5;
    const int wm = wid >> 2, wn = wid & 3;     // 4x4 warp grid; warp tile 32x32
    const int m = blockIdx.y;
    int t = blockIdx.x, I = 0;
    while (t >= BLK - I) { t -= BLK - I; I++; }
    const int J = I + t;
    uint32_t sbase = smem_u32(smem);

    float C[2][4][4];
#pragma unroll
    for (int a = 0; a < 2; a++)
#pragma unroll
        for (int b = 0; b < 4; b++)
#pragma unroll
            for (int c = 0; c < 4; c++) C[a][b][c] = 0.f;

    load_chunk(sbase, 0, m, I, J, 0, tid);
    load_chunk(sbase, 1, m, I, J, 1, tid);
    for (int c = 0; c < 12; c++) {
        int buf = c % NSTAGE;
        if (c + 2 < 12) {
            load_chunk(sbase, (c + 2) % NSTAGE, m, I, J, c + 2, tid);
            asm volatile("cp.async.wait_group 2;" ::: "memory");
        } else {
            asm volatile("cp.async.wait_group 0;" ::: "memory");
        }
        __syncthreads();
        uint32_t Abase = sbase + buf * STAGE_SZ;
        uint32_t Bbase = Abase + STAGE_OP;
#pragma unroll
        for (int ks = 0; ks < 4; ks++) {
            uint32_t a[2][4], b[2][4];
#pragma unroll
            for (int mi = 0; mi < 2; mi++) {
                uint32_t addr = Abase + (wm * 32 + mi * 16 + (lane & 15)) * PITCH
                              + (ks * 16 + (lane >> 4) * 8) * 2;
                asm volatile("ldmatrix.sync.aligned.m8n8.x4.shared.b16 {%0,%1,%2,%3}, [%4];"
                    : "=r"(a[mi][0]), "=r"(a[mi][1]), "=r"(a[mi][2]), "=r"(a[mi][3]) : "r"(addr));
            }
#pragma unroll
            for (int nP = 0; nP < 2; nP++) {
                int g = lane >> 3;
                uint32_t addr = Bbase + (wn * 32 + (nP * 2 + (g >> 1)) * 8 + (lane & 7)) * PITCH
                              + (ks * 16 + (g & 1) * 8) * 2;
                asm volatile("ldmatrix.sync.aligned.m8n8.x4.shared.b16 {%0,%1,%2,%3}, [%4];"
                    : "=r"(b[nP][0]), "=r"(b[nP][1]), "=r"(b[nP][2]), "=r"(b[nP][3]) : "r"(addr));
            }
#pragma unroll
            for (int mi = 0; mi < 2; mi++)
#pragma unroll
                for (int ni = 0; ni < 4; ni++) {
                    uint32_t b0 = b[ni >> 1][(ni & 1) * 2];
                    uint32_t b1 = b[ni >> 1][(ni & 1) * 2 + 1];
                    asm volatile(
                        "mma.sync.aligned.m16n8k16.row.col.f32.bf16.bf16.f32 "
                        "{%0,%1,%2,%3}, {%4,%5,%6,%7}, {%8,%9}, {%0,%1,%2,%3};"
                        : "+f"(C[mi][ni][0]), "+f"(C[mi][ni][1]),
                          "+f"(C[mi][ni][2]), "+f"(C[mi][ni][3])
                        : "r"(a[mi][0]), "r"(a[mi][1]), "r"(a[mi][2]), "r"(a[mi][3]),
                          "r"(b0), "r"(b1));
                }
        }
        __syncthreads();
    }

    // ---------- epilogue: row/col exp & raw sums ----------
    const float OFF = (m == 0) ? 5.f : 0.f;
    const bool lm = (I < 24) == (J < 24);
    float rE[4], rR[4], cE[8], cR[8];
#pragma unroll
    for (int k = 0; k < 4; k++) { rE[k] = rR[k] = 0.f; }
#pragma unroll
    for (int k = 0; k < 8; k++) { cE[k] = cR[k] = 0.f; }
#pragma unroll
    for (int mi = 0; mi < 2; mi++)
#pragma unroll
        for (int ni = 0; ni < 4; ni++)
#pragma unroll
            for (int f = 0; f < 4; f++) {
                int half = f >> 1, j = f & 1;
                float v = C[mi][ni][f];
                float e = __expf(5.f * v - OFF);
                rE[mi * 2 + half] += e; rR[mi * 2 + half] += v;
                cE[ni * 2 + j]    += e; cR[ni * 2 + j]    += v;
            }

    float* scRowE = (float*)smem;          // [128][4]
    float* scRowR = scRowE + 512;          // [128][4]
    float* scColE = scRowR + 512;          // [128][4]
    float* scColR = scColE + 512;          // [128][4]
#pragma unroll
    for (int k = 0; k < 4; k++) {
        float vE = rE[k], vR = rR[k];
        vE += __shfl_xor_sync(0xffffffffu, vE, 1);
        vE += __shfl_xor_sync(0xffffffffu, vE, 2);
        vR += __shfl_xor_sync(0xffffffffu, vR, 1);
        vR += __shfl_xor_sync(0xffffffffu, vR, 2);
        if ((lane & 3) == 0) {
            int r = wm * 32 + (k >> 1) * 16 + (k & 1) * 8 + (lane >> 2);
            scRowE[r * 4 + wn] = vE;
            scRowR[r * 4 + wn] = vR;
        }
    }
#pragma unroll
    for (int k = 0; k < 8; k++) {
        float vE = cE[k], vR = cR[k];
        vE += __shfl_xor_sync(0xffffffffu, vE, 4);
        vE += __shfl_xor_sync(0xffffffffu, vE, 8);
        vE += __shfl_xor_sync(0xffffffffu, vE, 16);
        vR += __shfl_xor_sync(0xffffffffu, vR, 4);
        vR += __shfl_xor_sync(0xffffffffu, vR, 8);
        vR += __shfl_xor_sync(0xffffffffu, vR, 16);
        if (lane < 4) {
            int cc = wn * 32 + (k >> 1) * 8 + (lane & 3) * 2 + (k & 1);
            scColE[cc * 4 + wm] = vE;
            scColR[cc * 4 + wm] = vR;
        }
    }
    __syncthreads();
    if (tid < 128) {
        int r = tid;
        float sE = scRowE[r * 4] + scRowE[r * 4 + 1] + scRowE[r * 4 + 2] + scRowE[r * 4 + 3];
        float sR = scRowR[r * 4] + scRowR[r * 4 + 1] + scRowR[r * 4 + 2] + scRowR[r * 4 + 3];
        g_spart[m][J][I * 128 + r] = sE;
        if (m == 0) g_tpart[J][I * 128 + r] = lm ? sR : 0.f;
    } else if (tid < 256 && I != J) {
        int cc = tid - 128;
        float sE = scColE[cc * 4] + scColE[cc * 4 + 1] + scColE[cc * 4 + 2] + scColE[cc * 4 + 3];
        float sR = scColR[cc * 4] + scColR[cc * 4 + 1] + scColR[cc * 4 + 2] + scColR[cc * 4 + 3];
        g_spart[m][I][J * 128 + cc] = sE;
        if (m == 0) g_tpart[I][J * 128 + cc] = lm ? sR : 0.f;
    }
}

// ---------------- sup finalize ----------------
__global__ void __launch_bounds__(256) supfin_kernel() {
    __shared__ float sm[256];
    int row = blockIdx.x * 256 + threadIdx.x;  // 24 blocks
    float s = 0.f, t = 0.f;
#pragma unroll
    for (int o = 0; o < BLK; o++) { s += g_spart[0][o][row]; t += g_tpart[o][row]; }
    float denom = s - 1.0f + 1e-12f;           // remove diagonal exp(0)=1
    float loss = logf(denom) + 5.0f - (5.0f * t - 5.0f) / 3071.0f;
    float r = blk_reduce(loss, sm);
    if (threadIdx.x == 0) g_sup_part[blockIdx.x] = r;
}

// ---------------- unsup finalize ----------------
__global__ void __launch_bounds__(256) unfin_kernel() {
    __shared__ float sm[256];
    int gw = (blockIdx.x * 256 + threadIdx.x) >> 5;  // 2048 warps
    int lane = threadIdx.x & 31;
    float acc = 0.f;
    if (gw < UU) {
        int u = gw;
        const float4* r0 = g_zn[3 * u + 0];
        const float4* r1 = g_zn[3 * u + 1];
        const float4* r2 = g_zn[3 * u + 2];
        float4 a0 = r0[lane], a1 = r0[lane + 32];
        float4 b0 = r1[lane], b1 = r1[lane + 32];
        float4 c0 = r2[lane], c1 = r2[lane + 32];
        float d01 = a0.x * b0.x + a0.y * b0.y + a0.z * b0.z + a0.w * b0.w
                  + a1.x * b1.x + a1.y * b1.y + a1.z * b1.z + a1.w * b1.w;
        float d02 = a0.x * c0.x + a0.y * c0.y + a0.z * c0.z + a0.w * c0.w
                  + a1.x * c1.x + a1.y * c1.y + a1.z * c1.z + a1.w * c1.w;
        float d12 = b0.x * c0.x + b0.y * c0.y + b0.z * c0.z + b0.w * c0.w
                  + b1.x * c1.x + b1.y * c1.y + b1.z * c1.z + b1.w * c1.w;
#pragma unroll
        for (int o = 16; o > 0; o >>= 1) {
            d01 += __shfl_xor_sync(0xffffffffu, d01, o);
            d02 += __shfl_xor_sync(0xffffffffu, d02, o);
            d12 += __shfl_xor_sync(0xffffffffu, d12, o);
        }
        if (lane == 0) {
            float e5 = __expf(5.0f);
            float s0 = 0.f, s1 = 0.f, s2 = 0.f;
#pragma unroll
            for (int o = 0; o < BLK; o++) {
                s0 += g_spart[1][o][3 * u + 0];
                s1 += g_spart[1][o][3 * u + 1];
                s2 += g_spart[1][o][3 * u + 2];
            }
            float per0 = logf(s0 - e5 + 1e-12f) - 2.5f * (d01 + d02);
            float per1 = logf(s1 - e5 + 1e-12f) - 2.5f * (d01 + d12);
            float per2 = logf(s2 - e5 + 1e-12f) - 2.5f * (d02 + d12);
            acc = per0 + per1 + per2;
        }
    }
    float r = blk_reduce(acc, sm);
    if (threadIdx.x == 0) g_un_part[blockIdx.x] = r;
}

// ---------------- final merge ----------------
__global__ void __launch_bounds__(256) final_kernel(float* __restrict__ out) {
    __shared__ float sm[256];
    int tid = threadIdx.x;
    float c0 = blk_reduce((tid < BCE_BLOCKS) ? g_bce_part[tid][0] : 0.f, sm);
    float c1 = blk_reduce((tid < BCE_BLOCKS) ? g_bce_part[tid][1] : 0.f, sm);
    float c2 = blk_reduce((tid < BCE_BLOCKS) ? g_bce_part[tid][2] : 0.f, sm);
    float c3 = blk_reduce((tid < BCE_BLOCKS) ? g_bce_part[tid][3] : 0.f, sm);
    float cnt = blk_reduce((tid < BCE_BLOCKS) ? g_bce_part[tid][4] : 0.f, sm);
    float sup_sum = blk_reduce((tid < 24) ? g_sup_part[tid] : 0.f, sm);
    float un_sum = blk_reduce(g_un_part[tid], sm);
    if (tid == 0) {
        float denom = fmaxf(cnt, 1.0f);
        float main_loss = c0 / denom;
        float view_loss = (c1 + c2 + c3) / (3.0f * denom);
        float sup_loss = sup_sum / (float)MM;
        float un_loss = un_sum / (float)MM;
        float total = main_loss + view_loss + sup_loss + 0.2f * un_loss;
        out[0] = total;
        out[1] = main_loss;
        out[2] = view_loss;
        out[3] = sup_loss;
        out[4] = un_loss;
    }
}

// ---------------- launch ----------------
extern "C" void kernel_launch(void* const* d_in, const int* in_sizes, int n_in,
                              void* d_out, int out_size) {
    const float* fused = (const float*)d_in[0];
    const float* vlg   = (const float*)d_in[1];
    const float* proj  = (const float*)d_in[2];
    const float* lab   = (const float*)d_in[3];
    const void*  maskp = d_in[4];
    const int*   pos   = (const int*)d_in[5];
    const int*   neg   = (const int*)d_in[6];
    const int*   unl   = (const int*)d_in[7];
    float* out = (float*)d_out;
    int n = in_sizes[0];

    cudaFuncSetAttribute(simmma_kernel, cudaFuncAttributeMaxDynamicSharedMemorySize, SMEM_DYN);

    detect_mask_kernel<<<1, 32>>>((const unsigned char*)maskp);
    bce_kernel<<<BCE_BLOCKS, 256>>>(fused, vlg, lab, maskp, n);
    gather_kernel<<<(2 * MM * 32) / 256, 256>>>(proj, pos, neg, unl);
    simmma_kernel<<<dim3(NTILE, 2), 512, SMEM_DYN>>>();
    supfin_kernel<<<MM / 256, 256>>>();
    unfin_kernel<<<(UU * 32) / 256, 256>>>();
    final_kernel<<<1, 256>>>(out);
}

// round 6
// speedup vs baseline: 3.2191x; 1.0342x over previous
#include <cuda_runtime.h>
#include <cuda_bf16.h>
#include <stdint.h>

// ---------------- problem constants ----------------
#define NN      100000
#define DD      256
#define PP      1024
#define UU      2048
#define MM      6144          // rows per similarity matrix (2048*3)
#define BLK     48            // 6144/128 row blocks
#define NTILE   1176          // 48*49/2 upper-tri tiles
#define BCE_BLOCKS 128

#define PITCH   144           // padded smem row bytes (64 bf16 -> 128B + 16 pad)
#define STAGE_OP (128 * PITCH)        // 18432 bytes per tile
#define STAGE_SZ (4 * STAGE_OP)       // 73728 per stage (h_I, l_I, h_J, l_J)
#define NSTAGE  2
#define SMEM_DYN (NSTAGE * STAGE_SZ)  // 147456

// ---------------- device scratch ----------------
__device__ __align__(16) __nv_bfloat16 g_hl[2][2][MM][DD]; // [mat][h/l][row][col]
__device__ float4 g_zn[MM][64];                 // unsup renormalized fp32 rows
__device__ float  g_spart[2][BLK][MM];          // per-(otherblock,row) sum of exp
__device__ float  g_tpart[BLK][MM];             // per-(otherblock,row) sum of dot (sup)
__device__ float  g_bce_part[BCE_BLOCKS][5];
__device__ float  g_sup_part[24];
__device__ float  g_un_part[256];
__device__ int    g_maskmode;

// ---------------- helpers ----------------
__device__ __forceinline__ uint32_t smem_u32(const void* p) {
    uint32_t a;
    asm("{ .reg .u64 t; cvta.to.shared.u64 t, %1; cvt.u32.u64 %0, t; }" : "=r"(a) : "l"(p));
    return a;
}

__device__ __forceinline__ float blk_reduce(float v, float* sm) {
    int tid = threadIdx.x;
    sm[tid] = v; __syncthreads();
#pragma unroll
    for (int s = 128; s > 0; s >>= 1) {
        if (tid < s) sm[tid] += sm[tid + s];
        __syncthreads();
    }
    float r = sm[0]; __syncthreads();
    return r;
}

// ---------------- mask dtype detection ----------------
__global__ void detect_mask_kernel(const unsigned char* m) {
    if (threadIdx.x == 0 && blockIdx.x == 0) {
        bool nonbin = false, oddone = false;
        for (int i = 0; i < 256; i++) {
            unsigned char b = m[i];
            if (b > 1) nonbin = true;
            else if (b == 1 && (i & 3)) oddone = true;
        }
        g_maskmode = nonbin ? 2 : (oddone ? 1 : 0);
    }
}

// ---------------- BCE partial sums ----------------
__global__ void __launch_bounds__(256) bce_kernel(const float* __restrict__ fused,
                                                  const float* __restrict__ vlg,
                                                  const float* __restrict__ lab,
                                                  const void* __restrict__ maskp,
                                                  int n) {
    __shared__ float sm[256];
    int mode = g_maskmode;
    float s_main = 0.f, s_v0 = 0.f, s_v1 = 0.f, s_v2 = 0.f, s_cnt = 0.f;
    for (int i = blockIdx.x * blockDim.x + threadIdx.x; i < n; i += gridDim.x * blockDim.x) {
        float mv;
        if (mode == 2)      mv = (((const float*)maskp)[i] != 0.f) ? 1.f : 0.f;
        else if (mode == 1) mv = (((const unsigned char*)maskp)[i] != 0) ? 1.f : 0.f;
        else                mv = (((const int*)maskp)[i] != 0) ? 1.f : 0.f;
        if (mv != 0.f) {
            float y = lab[i];
            float x = fused[i];
            s_main += fmaxf(x, 0.f) - x * y + log1pf(__expf(-fabsf(x)));
            x = vlg[i];
            s_v0 += fmaxf(x, 0.f) - x * y + log1pf(__expf(-fabsf(x)));
            x = vlg[NN + i];
            s_v1 += fmaxf(x, 0.f) - x * y + log1pf(__expf(-fabsf(x)));
            x = vlg[2 * NN + i];
            s_v2 += fmaxf(x, 0.f) - x * y + log1pf(__expf(-fabsf(x)));
            s_cnt += 1.f;
        }
    }
    float r;
    r = blk_reduce(s_main, sm); if (threadIdx.x == 0) g_bce_part[blockIdx.x][0] = r;
    r = blk_reduce(s_v0, sm);   if (threadIdx.x == 0) g_bce_part[blockIdx.x][1] = r;
    r = blk_reduce(s_v1, sm);   if (threadIdx.x == 0) g_bce_part[blockIdx.x][2] = r;
    r = blk_reduce(s_v2, sm);   if (threadIdx.x == 0) g_bce_part[blockIdx.x][3] = r;
    r = blk_reduce(s_cnt, sm);  if (threadIdx.x == 0) g_bce_part[blockIdx.x][4] = r;
}

// ---------------- gather: bf16 h/l split rows ----------------
__device__ __forceinline__ void store_hl(int mat, int row, int k0, float4 v) {
    __nv_bfloat16 h0 = __float2bfloat16(v.x), h1 = __float2bfloat16(v.y);
    __nv_bfloat16 h2 = __float2bfloat16(v.z), h3 = __float2bfloat16(v.w);
    __nv_bfloat16 l0 = __float2bfloat16(v.x - __bfloat162float(h0));
    __nv_bfloat16 l1 = __float2bfloat16(v.y - __bfloat162float(h1));
    __nv_bfloat16 l2 = __float2bfloat16(v.z - __bfloat162float(h2));
    __nv_bfloat16 l3 = __float2bfloat16(v.w - __bfloat162float(h3));
    uint2 hp, lp;
    hp.x = (uint32_t)__bfloat16_as_ushort(h0) | ((uint32_t)__bfloat16_as_ushort(h1) << 16);
    hp.y = (uint32_t)__bfloat16_as_ushort(h2) | ((uint32_t)__bfloat16_as_ushort(h3) << 16);
    lp.x = (uint32_t)__bfloat16_as_ushort(l0) | ((uint32_t)__bfloat16_as_ushort(l1) << 16);
    lp.y = (uint32_t)__bfloat16_as_ushort(l2) | ((uint32_t)__bfloat16_as_ushort(l3) << 16);
    *(uint2*)&g_hl[mat][0][row][k0] = hp;
    *(uint2*)&g_hl[mat][1][row][k0] = lp;
}

__global__ void __launch_bounds__(256) gather_kernel(const float* __restrict__ proj,
                                                     const int* __restrict__ pos,
                                                     const int* __restrict__ neg,
                                                     const int* __restrict__ unl) {
    int gw = (blockIdx.x * blockDim.x + threadIdx.x) >> 5;
    int lane = threadIdx.x & 31;
    if (gw >= 2 * MM) return;
    int mat = (gw >= MM) ? 1 : 0;
    int row = gw - mat * MM;
    int l = row / 3, v = row % 3;
    int idx;
    if (mat == 0) idx = (l < PP) ? pos[l] : neg[l - PP];
    else          idx = unl[l];
    const float4* src = (const float4*)(proj + ((size_t)v * NN + (size_t)idx) * DD);
    float4 x0 = src[lane];
    float4 x1 = src[lane + 32];
    if (mat == 1) {
        float ss = x0.x * x0.x + x0.y * x0.y + x0.z * x0.z + x0.w * x0.w
                 + x1.x * x1.x + x1.y * x1.y + x1.z * x1.z + x1.w * x1.w;
#pragma unroll
        for (int o = 16; o > 0; o >>= 1) ss += __shfl_xor_sync(0xffffffffu, ss, o);
        float inv = 1.f / (sqrtf(ss) + 1e-8f);
        x0.x *= inv; x0.y *= inv; x0.z *= inv; x0.w *= inv;
        x1.x *= inv; x1.y *= inv; x1.z *= inv; x1.w *= inv;
        g_zn[row][lane]      = x0;
        g_zn[row][lane + 32] = x1;
    }
    store_hl(mat, row, 4 * lane, x0);
    store_hl(mat, row, 128 + 4 * lane, x1);
}

// ---------------- HMMA similarity kernel (upper-triangular tiles) ----------------
// Per k-slice loads 4 tiles (h_I, l_I, h_J, l_J): 4608 x 16B = 8 cp.async per thread.
__device__ __forceinline__ void load_stage(uint32_t sbase, int stage, int m, int I, int J,
                                           int kk, int tid) {
    const __nv_bfloat16* b0 = &g_hl[m][0][I * 128][kk * 64];
    const __nv_bfloat16* b1 = &g_hl[m][1][I * 128][kk * 64];
    const __nv_bfloat16* b2 = &g_hl[m][0][J * 128][kk * 64];
    const __nv_bfloat16* b3 = &g_hl[m][1][J * 128][kk * 64];
    uint32_t sb = sbase + stage * STAGE_SZ;
#pragma unroll
    for (int i = 0; i < 8; i++) {
        int idx = tid * 8 + i;
        int op = idx >> 10, rc = idx & 1023, row = rc >> 3, c16 = rc & 7;
        const __nv_bfloat16* src =
            (op == 0 ? b0 : op == 1 ? b1 : op == 2 ? b2 : b3) + row * DD + c16 * 8;
        uint32_t dst = sb + op * STAGE_OP + row * PITCH + c16 * 16;
        asm volatile("cp.async.cg.shared.global [%0], [%1], 16;" :: "r"(dst), "l"(src));
    }
    asm volatile("cp.async.commit_group;" ::: "memory");
}

#define MMA8(CC, AA, B0, B1)                                                   \
    asm volatile(                                                              \
        "mma.sync.aligned.m16n8k16.row.col.f32.bf16.bf16.f32 "                 \
        "{%0,%1,%2,%3}, {%4,%5,%6,%7}, {%8,%9}, {%0,%1,%2,%3};"                \
        : "+f"((CC)[0]), "+f"((CC)[1]), "+f"((CC)[2]), "+f"((CC)[3])           \
        : "r"((AA)[0]), "r"((AA)[1]), "r"((AA)[2]), "r"((AA)[3]),              \
          "r"(B0), "r"(B1))

__global__ void __launch_bounds__(512, 1) simmma_kernel() {
    extern __shared__ __align__(16) unsigned char smem[];
    const int tid = threadIdx.x, lane = tid & 31, wid = tid >> 5;
    const int wm = wid >> 2, wn = wid & 3;     // 4x4 warp grid; warp tile 32x32
    const int m = blockIdx.y;
    int t = blockIdx.x, I = 0;
    while (t >= BLK - I) { t -= BLK - I; I++; }
    const int J = I + t;
    uint32_t sbase = smem_u32(smem);

    float C[2][4][4];
#pragma unroll
    for (int a = 0; a < 2; a++)
#pragma unroll
        for (int b = 0; b < 4; b++)
#pragma unroll
            for (int c = 0; c < 4; c++) C[a][b][c] = 0.f;

    load_stage(sbase, 0, m, I, J, 0, tid);
    for (int kk = 0; kk < 4; kk++) {
        int buf = kk & 1;
        if (kk + 1 < 4) {
            load_stage(sbase, buf ^ 1, m, I, J, kk + 1, tid);
            asm volatile("cp.async.wait_group 1;" ::: "memory");
        } else {
            asm volatile("cp.async.wait_group 0;" ::: "memory");
        }
        __syncthreads();
        uint32_t AH = sbase + buf * STAGE_SZ;
        uint32_t AL = AH + STAGE_OP;
        uint32_t BH = AH + 2 * STAGE_OP;
        uint32_t BL = AH + 3 * STAGE_OP;
#pragma unroll
        for (int ks = 0; ks < 4; ks++) {
            uint32_t ah[2][4], al[2][4], bh[2][4], bl[2][4];
#pragma unroll
            for (int mi = 0; mi < 2; mi++) {
                uint32_t off = (wm * 32 + mi * 16 + (lane & 15)) * PITCH
                             + (ks * 16 + (lane >> 4) * 8) * 2;
                asm volatile("ldmatrix.sync.aligned.m8n8.x4.shared.b16 {%0,%1,%2,%3}, [%4];"
                    : "=r"(ah[mi][0]), "=r"(ah[mi][1]), "=r"(ah[mi][2]), "=r"(ah[mi][3])
                    : "r"(AH + off));
                asm volatile("ldmatrix.sync.aligned.m8n8.x4.shared.b16 {%0,%1,%2,%3}, [%4];"
                    : "=r"(al[mi][0]), "=r"(al[mi][1]), "=r"(al[mi][2]), "=r"(al[mi][3])
                    : "r"(AL + off));
            }
#pragma unroll
            for (int nP = 0; nP < 2; nP++) {
                int g = lane >> 3;
                uint32_t off = (wn * 32 + (nP * 2 + (g >> 1)) * 8 + (lane & 7)) * PITCH
                             + (ks * 16 + (g & 1) * 8) * 2;
                asm volatile("ldmatrix.sync.aligned.m8n8.x4.shared.b16 {%0,%1,%2,%3}, [%4];"
                    : "=r"(bh[nP][0]), "=r"(bh[nP][1]), "=r"(bh[nP][2]), "=r"(bh[nP][3])
                    : "r"(BH + off));
                asm volatile("ldmatrix.sync.aligned.m8n8.x4.shared.b16 {%0,%1,%2,%3}, [%4];"
                    : "=r"(bl[nP][0]), "=r"(bl[nP][1]), "=r"(bl[nP][2]), "=r"(bl[nP][3])
                    : "r"(BL + off));
            }
#pragma unroll
            for (int mi = 0; mi < 2; mi++)
#pragma unroll
                for (int ni = 0; ni < 4; ni++) {
                    int p = ni >> 1, q2 = (ni & 1) * 2;
                    MMA8(C[mi][ni], ah[mi], bh[p][q2], bh[p][q2 + 1]);   // h.h
                    MMA8(C[mi][ni], ah[mi], bl[p][q2], bl[p][q2 + 1]);   // h.l
                    MMA8(C[mi][ni], al[mi], bh[p][q2], bh[p][q2 + 1]);   // l.h
                }
        }
        __syncthreads();
    }

    // ---------- epilogue: row/col exp & raw sums ----------
    const float OFF = (m == 0) ? 5.f : 0.f;
    const bool lm = (I < 24) == (J < 24);
    float rE[4], rR[4], cE[8], cR[8];
#pragma unroll
    for (int k = 0; k < 4; k++) { rE[k] = rR[k] = 0.f; }
#pragma unroll
    for (int k = 0; k < 8; k++) { cE[k] = cR[k] = 0.f; }
#pragma unroll
    for (int mi = 0; mi < 2; mi++)
#pragma unroll
        for (int ni = 0; ni < 4; ni++)
#pragma unroll
            for (int f = 0; f < 4; f++) {
                int half = f >> 1, j = f & 1;
                float v = C[mi][ni][f];
                float e = __expf(5.f * v - OFF);
                rE[mi * 2 + half] += e; rR[mi * 2 + half] += v;
                cE[ni * 2 + j]    += e; cR[ni * 2 + j]    += v;
            }

    float* scRowE = (float*)smem;          // [128][4]
    float* scRowR = scRowE + 512;          // [128][4]
    float* scColE = scRowR + 512;          // [128][4]
    float* scColR = scColE + 512;          // [128][4]
#pragma unroll
    for (int k = 0; k < 4; k++) {
        float vE = rE[k], vR = rR[k];
        vE += __shfl_xor_sync(0xffffffffu, vE, 1);
        vE += __shfl_xor_sync(0xffffffffu, vE, 2);
        vR += __shfl_xor_sync(0xffffffffu, vR, 1);
        vR += __shfl_xor_sync(0xffffffffu, vR, 2);
        if ((lane & 3) == 0) {
            int r = wm * 32 + (k >> 1) * 16 + (k & 1) * 8 + (lane >> 2);
            scRowE[r * 4 + wn] = vE;
            scRowR[r * 4 + wn] = vR;
        }
    }
#pragma unroll
    for (int k = 0; k < 8; k++) {
        float vE = cE[k], vR = cR[k];
        vE += __shfl_xor_sync(0xffffffffu, vE, 4);
        vE += __shfl_xor_sync(0xffffffffu, vE, 8);
        vE += __shfl_xor_sync(0xffffffffu, vE, 16);
        vR += __shfl_xor_sync(0xffffffffu, vR, 4);
        vR += __shfl_xor_sync(0xffffffffu, vR, 8);
        vR += __shfl_xor_sync(0xffffffffu, vR, 16);
        if (lane < 4) {
            int cc = wn * 32 + (k >> 1) * 8 + (lane & 3) * 2 + (k & 1);
            scColE[cc * 4 + wm] = vE;
            scColR[cc * 4 + wm] = vR;
        }
    }
    __syncthreads();
    if (tid < 128) {
        int r = tid;
        float sE = scRowE[r * 4] + scRowE[r * 4 + 1] + scRowE[r * 4 + 2] + scRowE[r * 4 + 3];
        float sR = scRowR[r * 4] + scRowR[r * 4 + 1] + scRowR[r * 4 + 2] + scRowR[r * 4 + 3];
        g_spart[m][J][I * 128 + r] = sE;
        if (m == 0) g_tpart[J][I * 128 + r] = lm ? sR : 0.f;
    } else if (tid < 256 && I != J) {
        int cc = tid - 128;
        float sE = scColE[cc * 4] + scColE[cc * 4 + 1] + scColE[cc * 4 + 2] + scColE[cc * 4 + 3];
        float sR = scColR[cc * 4] + scColR[cc * 4 + 1] + scColR[cc * 4 + 2] + scColR[cc * 4 + 3];
        g_spart[m][I][J * 128 + cc] = sE;
        if (m == 0) g_tpart[I][J * 128 + cc] = lm ? sR : 0.f;
    }
}

// ---------------- sup finalize ----------------
__global__ void __launch_bounds__(256) supfin_kernel() {
    __shared__ float sm[256];
    int row = blockIdx.x * 256 + threadIdx.x;  // 24 blocks
    float s = 0.f, t = 0.f;
#pragma unroll
    for (int o = 0; o < BLK; o++) { s += g_spart[0][o][row]; t += g_tpart[o][row]; }
    float denom = s - 1.0f + 1e-12f;           // remove diagonal exp(0)=1
    float loss = logf(denom) + 5.0f - (5.0f * t - 5.0f) / 3071.0f;
    float r = blk_reduce(loss, sm);
    if (threadIdx.x == 0) g_sup_part[blockIdx.x] = r;
}

// ---------------- unsup finalize ----------------
__global__ void __launch_bounds__(256) unfin_kernel() {
    __shared__ float sm[256];
    int gw = (blockIdx.x * 256 + threadIdx.x) >> 5;  // 2048 warps
    int lane = threadIdx.x & 31;
    float acc = 0.f;
    if (gw < UU) {
        int u = gw;
        const float4* r0 = g_zn[3 * u + 0];
        const float4* r1 = g_zn[3 * u + 1];
        const float4* r2 = g_zn[3 * u + 2];
        float4 a0 = r0[lane], a1 = r0[lane + 32];
        float4 b0 = r1[lane], b1 = r1[lane + 32];
        float4 c0 = r2[lane], c1 = r2[lane + 32];
        float d01 = a0.x * b0.x + a0.y * b0.y + a0.z * b0.z + a0.w * b0.w
                  + a1.x * b1.x + a1.y * b1.y + a1.z * b1.z + a1.w * b1.w;
        float d02 = a0.x * c0.x + a0.y * c0.y + a0.z * c0.z + a0.w * c0.w
                  + a1.x * c1.x + a1.y * c1.y + a1.z * c1.z + a1.w * c1.w;
        float d12 = b0.x * c0.x + b0.y * c0.y + b0.z * c0.z + b0.w * c0.w
                  + b1.x * c1.x + b1.y * c1.y + b1.z * c1.z + b1.w * c1.w;
#pragma unroll
        for (int o = 16; o > 0; o >>= 1) {
            d01 += __shfl_xor_sync(0xffffffffu, d01, o);
            d02 += __shfl_xor_sync(0xffffffffu, d02, o);
            d12 += __shfl_xor_sync(0xffffffffu, d12, o);
        }
        if (lane == 0) {
            float e5 = __expf(5.0f);
            float s0 = 0.f, s1 = 0.f, s2 = 0.f;
#pragma unroll
            for (int o = 0; o < BLK; o++) {
                s0 += g_spart[1][o][3 * u + 0];
                s1 += g_spart[1][o][3 * u + 1];
                s2 += g_spart[1][o][3 * u + 2];
            }
            float per0 = logf(s0 - e5 + 1e-12f) - 2.5f * (d01 + d02);
            float per1 = logf(s1 - e5 + 1e-12f) - 2.5f * (d01 + d12);
            float per2 = logf(s2 - e5 + 1e-12f) - 2.5f * (d02 + d12);
            acc = per0 + per1 + per2;
        }
    }
    float r = blk_reduce(acc, sm);
    if (threadIdx.x == 0) g_un_part[blockIdx.x] = r;
}

// ---------------- final merge ----------------
__global__ void __launch_bounds__(256) final_kernel(float* __restrict__ out) {
    __shared__ float sm[256];
    int tid = threadIdx.x;
    float c0 = blk_reduce((tid < BCE_BLOCKS) ? g_bce_part[tid][0] : 0.f, sm);
    float c1 = blk_reduce((tid < BCE_BLOCKS) ? g_bce_part[tid][1] : 0.f, sm);
    float c2 = blk_reduce((tid < BCE_BLOCKS) ? g_bce_part[tid][2] : 0.f, sm);
    float c3 = blk_reduce((tid < BCE_BLOCKS) ? g_bce_part[tid][3] : 0.f, sm);
    float cnt = blk_reduce((tid < BCE_BLOCKS) ? g_bce_part[tid][4] : 0.f, sm);
    float sup_sum = blk_reduce((tid < 24) ? g_sup_part[tid] : 0.f, sm);
    float un_sum = blk_reduce(g_un_part[tid], sm);
    if (tid == 0) {
        float denom = fmaxf(cnt, 1.0f);
        float main_loss = c0 / denom;
        float view_loss = (c1 + c2 + c3) / (3.0f * denom);
        float sup_loss = sup_sum / (float)MM;
        float un_loss = un_sum / (float)MM;
        float total = main_loss + view_loss + sup_loss + 0.2f * un_loss;
        out[0] = total;
        out[1] = main_loss;
        out[2] = view_loss;
        out[3] = sup_loss;
        out[4] = un_loss;
    }
}

// ---------------- launch ----------------
extern "C" void kernel_launch(void* const* d_in, const int* in_sizes, int n_in,
                              void* d_out, int out_size) {
    const float* fused = (const float*)d_in[0];
    const float* vlg   = (const float*)d_in[1];
    const float* proj  = (const float*)d_in[2];
    const float* lab   = (const float*)d_in[3];
    const void*  maskp = d_in[4];
    const int*   pos   = (const int*)d_in[5];
    const int*   neg   = (const int*)d_in[6];
    const int*   unl   = (const int*)d_in[7];
    float* out = (float*)d_out;
    int n = in_sizes[0];

    cudaFuncSetAttribute(simmma_kernel, cudaFuncAttributeMaxDynamicSharedMemorySize, SMEM_DYN);

    detect_mask_kernel<<<1, 32>>>((const unsigned char*)maskp);
    bce_kernel<<<BCE_BLOCKS, 256>>>(fused, vlg, lab, maskp, n);
    gather_kernel<<<(2 * MM * 32) / 256, 256>>>(proj, pos, neg, unl);
    simmma_kernel<<<dim3(NTILE, 2), 512, SMEM_DYN>>>();
    supfin_kernel<<<MM / 256, 256>>>();
    unfin_kernel<<<(UU * 32) / 256, 256>>>();
    final_kernel<<<1, 256>>>(out);
}

// round 7
// speedup vs baseline: 3.3060x; 1.0270x over previous
#include <cuda_runtime.h>
#include <cuda_bf16.h>
#include <stdint.h>

// ---------------- problem constants ----------------
#define NN      100000
#define DD      256
#define PP      1024
#define UU      2048
#define MM      6144          // rows per similarity matrix (2048*3)
#define BLK     48            // 6144/128 row blocks
#define NTILE   1176          // 48*49/2 upper-tri tiles
#define BCE_BLOCKS 128

#define PITCH   144           // padded smem row bytes (64 bf16 -> 128B + 16 pad)
#define STAGE_OP (128 * PITCH)        // 18432 bytes per tile
#define STAGE_SZ (4 * STAGE_OP)       // 73728 per stage (h_I, l_I, h_J, l_J)
#define NSTAGE  2
#define SMEM_DYN (NSTAGE * STAGE_SZ)  // 147456

// ---------------- device scratch ----------------
__device__ __align__(16) __nv_bfloat16 g_hl[2][2][MM][DD]; // [mat][h/l][row][col]
__device__ float4 g_zn[MM][64];                 // unsup renormalized fp32 rows
__device__ float  g_spart[2][BLK][MM];          // per-(otherblock,row) sum of exp
__device__ float  g_tpart[BLK][MM];             // per-(otherblock,row) sum of dot (sup)
__device__ float  g_bce_part[BCE_BLOCKS][5];
__device__ float  g_sup_part[24];
__device__ float  g_un_part[256];
__device__ int    g_maskmode;

// ---------------- helpers ----------------
__device__ __forceinline__ uint32_t smem_u32(const void* p) {
    uint32_t a;
    asm("{ .reg .u64 t; cvta.to.shared.u64 t, %1; cvt.u32.u64 %0, t; }" : "=r"(a) : "l"(p));
    return a;
}

__device__ __forceinline__ float blk_reduce(float v, float* sm) {
    int tid = threadIdx.x;
    sm[tid] = v; __syncthreads();
#pragma unroll
    for (int s = 128; s > 0; s >>= 1) {
        if (tid < s) sm[tid] += sm[tid + s];
        __syncthreads();
    }
    float r = sm[0]; __syncthreads();
    return r;
}

// ---------------- mask dtype detection ----------------
__global__ void detect_mask_kernel(const unsigned char* m) {
    if (threadIdx.x == 0 && blockIdx.x == 0) {
        bool nonbin = false, oddone = false;
        for (int i = 0; i < 256; i++) {
            unsigned char b = m[i];
            if (b > 1) nonbin = true;
            else if (b == 1 && (i & 3)) oddone = true;
        }
        g_maskmode = nonbin ? 2 : (oddone ? 1 : 0);
    }
}

// ---------------- BCE partial sums ----------------
__global__ void __launch_bounds__(256) bce_kernel(const float* __restrict__ fused,
                                                  const float* __restrict__ vlg,
                                                  const float* __restrict__ lab,
                                                  const void* __restrict__ maskp,
                                                  int n) {
    __shared__ float sm[256];
    int mode = g_maskmode;
    float s_main = 0.f, s_v0 = 0.f, s_v1 = 0.f, s_v2 = 0.f, s_cnt = 0.f;
    for (int i = blockIdx.x * blockDim.x + threadIdx.x; i < n; i += gridDim.x * blockDim.x) {
        float mv;
        if (mode == 2)      mv = (((const float*)maskp)[i] != 0.f) ? 1.f : 0.f;
        else if (mode == 1) mv = (((const unsigned char*)maskp)[i] != 0) ? 1.f : 0.f;
        else                mv = (((const int*)maskp)[i] != 0) ? 1.f : 0.f;
        if (mv != 0.f) {
            float y = lab[i];
            float x = fused[i];
            s_main += fmaxf(x, 0.f) - x * y + log1pf(__expf(-fabsf(x)));
            x = vlg[i];
            s_v0 += fmaxf(x, 0.f) - x * y + log1pf(__expf(-fabsf(x)));
            x = vlg[NN + i];
            s_v1 += fmaxf(x, 0.f) - x * y + log1pf(__expf(-fabsf(x)));
            x = vlg[2 * NN + i];
            s_v2 += fmaxf(x, 0.f) - x * y + log1pf(__expf(-fabsf(x)));
            s_cnt += 1.f;
        }
    }
    float r;
    r = blk_reduce(s_main, sm); if (threadIdx.x == 0) g_bce_part[blockIdx.x][0] = r;
    r = blk_reduce(s_v0, sm);   if (threadIdx.x == 0) g_bce_part[blockIdx.x][1] = r;
    r = blk_reduce(s_v1, sm);   if (threadIdx.x == 0) g_bce_part[blockIdx.x][2] = r;
    r = blk_reduce(s_v2, sm);   if (threadIdx.x == 0) g_bce_part[blockIdx.x][3] = r;
    r = blk_reduce(s_cnt, sm);  if (threadIdx.x == 0) g_bce_part[blockIdx.x][4] = r;
}

// ---------------- gather: bf16 h/l split rows ----------------
__device__ __forceinline__ void store_hl(int mat, int row, int k0, float4 v) {
    __nv_bfloat16 h0 = __float2bfloat16(v.x), h1 = __float2bfloat16(v.y);
    __nv_bfloat16 h2 = __float2bfloat16(v.z), h3 = __float2bfloat16(v.w);
    __nv_bfloat16 l0 = __float2bfloat16(v.x - __bfloat162float(h0));
    __nv_bfloat16 l1 = __float2bfloat16(v.y - __bfloat162float(h1));
    __nv_bfloat16 l2 = __float2bfloat16(v.z - __bfloat162float(h2));
    __nv_bfloat16 l3 = __float2bfloat16(v.w - __bfloat162float(h3));
    uint2 hp, lp;
    hp.x = (uint32_t)__bfloat16_as_ushort(h0) | ((uint32_t)__bfloat16_as_ushort(h1) << 16);
    hp.y = (uint32_t)__bfloat16_as_ushort(h2) | ((uint32_t)__bfloat16_as_ushort(h3) << 16);
    lp.x = (uint32_t)__bfloat16_as_ushort(l0) | ((uint32_t)__bfloat16_as_ushort(l1) << 16);
    lp.y = (uint32_t)__bfloat16_as_ushort(l2) | ((uint32_t)__bfloat16_as_ushort(l3) << 16);
    *(uint2*)&g_hl[mat][0][row][k0] = hp;
    *(uint2*)&g_hl[mat][1][row][k0] = lp;
}

__global__ void __launch_bounds__(256) gather_kernel(const float* __restrict__ proj,
                                                     const int* __restrict__ pos,
                                                     const int* __restrict__ neg,
                                                     const int* __restrict__ unl) {
    int gw = (blockIdx.x * blockDim.x + threadIdx.x) >> 5;
    int lane = threadIdx.x & 31;
    if (gw >= 2 * MM) return;
    int mat = (gw >= MM) ? 1 : 0;
    int row = gw - mat * MM;
    int l = row / 3, v = row % 3;
    int idx;
    if (mat == 0) idx = (l < PP) ? pos[l] : neg[l - PP];
    else          idx = unl[l];
    const float4* src = (const float4*)(proj + ((size_t)v * NN + (size_t)idx) * DD);
    float4 x0 = src[lane];
    float4 x1 = src[lane + 32];
    if (mat == 1) {
        float ss = x0.x * x0.x + x0.y * x0.y + x0.z * x0.z + x0.w * x0.w
                 + x1.x * x1.x + x1.y * x1.y + x1.z * x1.z + x1.w * x1.w;
#pragma unroll
        for (int o = 16; o > 0; o >>= 1) ss += __shfl_xor_sync(0xffffffffu, ss, o);
        float inv = 1.f / (sqrtf(ss) + 1e-8f);
        x0.x *= inv; x0.y *= inv; x0.z *= inv; x0.w *= inv;
        x1.x *= inv; x1.y *= inv; x1.z *= inv; x1.w *= inv;
        g_zn[row][lane]      = x0;
        g_zn[row][lane + 32] = x1;
    }
    store_hl(mat, row, 4 * lane, x0);
    store_hl(mat, row, 128 + 4 * lane, x1);
}

// ---------------- HMMA similarity kernel (upper-triangular tiles) ----------------
// 1024 threads: 4096 x 16B per stage = 4 cp.async per thread.
__device__ __forceinline__ void load_stage(uint32_t sbase, int stage, int m, int I, int J,
                                           int kk, int tid) {
    const __nv_bfloat16* b0 = &g_hl[m][0][I * 128][kk * 64];
    const __nv_bfloat16* b1 = &g_hl[m][1][I * 128][kk * 64];
    const __nv_bfloat16* b2 = &g_hl[m][0][J * 128][kk * 64];
    const __nv_bfloat16* b3 = &g_hl[m][1][J * 128][kk * 64];
    uint32_t sb = sbase + stage * STAGE_SZ;
#pragma unroll
    for (int i = 0; i < 4; i++) {
        int idx = tid * 4 + i;
        int op = idx >> 10, rc = idx & 1023, row = rc >> 3, c16 = rc & 7;
        const __nv_bfloat16* src =
            (op == 0 ? b0 : op == 1 ? b1 : op == 2 ? b2 : b3) + row * DD + c16 * 8;
        uint32_t dst = sb + op * STAGE_OP + row * PITCH + c16 * 16;
        asm volatile("cp.async.cg.shared.global [%0], [%1], 16;" :: "r"(dst), "l"(src));
    }
    asm volatile("cp.async.commit_group;" ::: "memory");
}

#define MMA8(CC, AA, B0, B1)                                                   \
    asm volatile(                                                              \
        "mma.sync.aligned.m16n8k16.row.col.f32.bf16.bf16.f32 "                 \
        "{%0,%1,%2,%3}, {%4,%5,%6,%7}, {%8,%9}, {%0,%1,%2,%3};"                \
        : "+f"((CC)[0]), "+f"((CC)[1]), "+f"((CC)[2]), "+f"((CC)[3])           \
        : "r"((AA)[0]), "r"((AA)[1]), "r"((AA)[2]), "r"((AA)[3]),              \
          "r"(B0), "r"(B1))

__global__ void __launch_bounds__(1024, 1) simmma_kernel() {
    extern __shared__ __align__(16) unsigned char smem[];
    const int tid = threadIdx.x, lane = tid & 31, wid = tid >> 5;
    const int wm = wid >> 3, wn = wid & 7;     // 4x8 warp grid; warp tile 32x16
    const int m = blockIdx.y;
    int t = blockIdx.x, I = 0;
    while (t >= BLK - I) { t -= BLK - I; I++; }
    const int J = I + t;
    uint32_t sbase = smem_u32(smem);

    float C[2][2][4];
#pragma unroll
    for (int a = 0; a < 2; a++)
#pragma unroll
        for (int b = 0; b < 2; b++)
#pragma unroll
            for (int c = 0; c < 4; c++) C[a][b][c] = 0.f;

    load_stage(sbase, 0, m, I, J, 0, tid);
    for (int kk = 0; kk < 4; kk++) {
        int buf = kk & 1;
        if (kk + 1 < 4) {
            load_stage(sbase, buf ^ 1, m, I, J, kk + 1, tid);
            asm volatile("cp.async.wait_group 1;" ::: "memory");
        } else {
            asm volatile("cp.async.wait_group 0;" ::: "memory");
        }
        __syncthreads();
        uint32_t AH = sbase + buf * STAGE_SZ;
        uint32_t AL = AH + STAGE_OP;
        uint32_t BH = AH + 2 * STAGE_OP;
        uint32_t BL = AH + 3 * STAGE_OP;
#pragma unroll
        for (int ks = 0; ks < 4; ks++) {
            uint32_t ah[2][4], al[2][4], bh[4], bl[4];
#pragma unroll
            for (int mi = 0; mi < 2; mi++) {
                uint32_t off = (wm * 32 + mi * 16 + (lane & 15)) * PITCH
                             + (ks * 16 + (lane >> 4) * 8) * 2;
                asm volatile("ldmatrix.sync.aligned.m8n8.x4.shared.b16 {%0,%1,%2,%3}, [%4];"
                    : "=r"(ah[mi][0]), "=r"(ah[mi][1]), "=r"(ah[mi][2]), "=r"(ah[mi][3])
                    : "r"(AH + off));
                asm volatile("ldmatrix.sync.aligned.m8n8.x4.shared.b16 {%0,%1,%2,%3}, [%4];"
                    : "=r"(al[mi][0]), "=r"(al[mi][1]), "=r"(al[mi][2]), "=r"(al[mi][3])
                    : "r"(AL + off));
            }
            {
                int g = lane >> 3;
                uint32_t off = (wn * 16 + (g >> 1) * 8 + (lane & 7)) * PITCH
                             + (ks * 16 + (g & 1) * 8) * 2;
                asm volatile("ldmatrix.sync.aligned.m8n8.x4.shared.b16 {%0,%1,%2,%3}, [%4];"
                    : "=r"(bh[0]), "=r"(bh[1]), "=r"(bh[2]), "=r"(bh[3]) : "r"(BH + off));
                asm volatile("ldmatrix.sync.aligned.m8n8.x4.shared.b16 {%0,%1,%2,%3}, [%4];"
                    : "=r"(bl[0]), "=r"(bl[1]), "=r"(bl[2]), "=r"(bl[3]) : "r"(BL + off));
            }
#pragma unroll
            for (int mi = 0; mi < 2; mi++)
#pragma unroll
                for (int ni = 0; ni < 2; ni++) {
                    int q2 = ni * 2;
                    MMA8(C[mi][ni], ah[mi], bh[q2], bh[q2 + 1]);   // h.h
                    MMA8(C[mi][ni], ah[mi], bl[q2], bl[q2 + 1]);   // h.l
                    MMA8(C[mi][ni], al[mi], bh[q2], bh[q2 + 1]);   // l.h
                }
        }
        __syncthreads();
    }

    // ---------- epilogue: row/col exp & raw sums ----------
    const float OFF = (m == 0) ? 5.f : 0.f;
    const bool lm = (I < 24) == (J < 24);
    float rE[4], rR[4], cE[4], cR[4];
#pragma unroll
    for (int k = 0; k < 4; k++) { rE[k] = rR[k] = cE[k] = cR[k] = 0.f; }
#pragma unroll
    for (int mi = 0; mi < 2; mi++)
#pragma unroll
        for (int ni = 0; ni < 2; ni++)
#pragma unroll
            for (int f = 0; f < 4; f++) {
                int half = f >> 1, j = f & 1;
                float v = C[mi][ni][f];
                float e = __expf(5.f * v - OFF);
                rE[mi * 2 + half] += e; rR[mi * 2 + half] += v;
                cE[ni * 2 + j]    += e; cR[ni * 2 + j]    += v;
            }

    float* scRowE = (float*)smem;          // [128][8]
    float* scRowR = scRowE + 1024;         // [128][8]
    float* scColE = scRowR + 1024;         // [128][4]
    float* scColR = scColE + 512;          // [128][4]
#pragma unroll
    for (int k = 0; k < 4; k++) {
        float vE = rE[k], vR = rR[k];
        vE += __shfl_xor_sync(0xffffffffu, vE, 1);
        vE += __shfl_xor_sync(0xffffffffu, vE, 2);
        vR += __shfl_xor_sync(0xffffffffu, vR, 1);
        vR += __shfl_xor_sync(0xffffffffu, vR, 2);
        if ((lane & 3) == 0) {
            int r = wm * 32 + (k >> 1) * 16 + (k & 1) * 8 + (lane >> 2);
            scRowE[r * 8 + wn] = vE;
            scRowR[r * 8 + wn] = vR;
        }
    }
#pragma unroll
    for (int k = 0; k < 4; k++) {
        float vE = cE[k], vR = cR[k];
        vE += __shfl_xor_sync(0xffffffffu, vE, 4);
        vE += __shfl_xor_sync(0xffffffffu, vE, 8);
        vE += __shfl_xor_sync(0xffffffffu, vE, 16);
        vR += __shfl_xor_sync(0xffffffffu, vR, 4);
        vR += __shfl_xor_sync(0xffffffffu, vR, 8);
        vR += __shfl_xor_sync(0xffffffffu, vR, 16);
        if (lane < 4) {
            int cc = wn * 16 + (k >> 1) * 8 + (lane & 3) * 2 + (k & 1);
            scColE[cc * 4 + wm] = vE;
            scColR[cc * 4 + wm] = vR;
        }
    }
    __syncthreads();
    if (tid < 128) {
        int r = tid;
        float sE = 0.f, sR = 0.f;
#pragma unroll
        for (int x = 0; x < 8; x++) { sE += scRowE[r * 8 + x]; sR += scRowR[r * 8 + x]; }
        g_spart[m][J][I * 128 + r] = sE;
        if (m == 0) g_tpart[J][I * 128 + r] = lm ? sR : 0.f;
    } else if (tid < 256 && I != J) {
        int cc = tid - 128;
        float sE = scColE[cc * 4] + scColE[cc * 4 + 1] + scColE[cc * 4 + 2] + scColE[cc * 4 + 3];
        float sR = scColR[cc * 4] + scColR[cc * 4 + 1] + scColR[cc * 4 + 2] + scColR[cc * 4 + 3];
        g_spart[m][I][J * 128 + cc] = sE;
        if (m == 0) g_tpart[I][J * 128 + cc] = lm ? sR : 0.f;
    }
}

// ---------------- sup finalize ----------------
__global__ void __launch_bounds__(256) supfin_kernel() {
    __shared__ float sm[256];
    int row = blockIdx.x * 256 + threadIdx.x;  // 24 blocks
    float s = 0.f, t = 0.f;
#pragma unroll
    for (int o = 0; o < BLK; o++) { s += g_spart[0][o][row]; t += g_tpart[o][row]; }
    float denom = s - 1.0f + 1e-12f;           // remove diagonal exp(0)=1
    float loss = logf(denom) + 5.0f - (5.0f * t - 5.0f) / 3071.0f;
    float r = blk_reduce(loss, sm);
    if (threadIdx.x == 0) g_sup_part[blockIdx.x] = r;
}

// ---------------- unsup finalize ----------------
__global__ void __launch_bounds__(256) unfin_kernel() {
    __shared__ float sm[256];
    int gw = (blockIdx.x * 256 + threadIdx.x) >> 5;  // 2048 warps
    int lane = threadIdx.x & 31;
    float acc = 0.f;
    if (gw < UU) {
        int u = gw;
        const float4* r0 = g_zn[3 * u + 0];
        const float4* r1 = g_zn[3 * u + 1];
        const float4* r2 = g_zn[3 * u + 2];
        float4 a0 = r0[lane], a1 = r0[lane + 32];
        float4 b0 = r1[lane], b1 = r1[lane + 32];
        float4 c0 = r2[lane], c1 = r2[lane + 32];
        float d01 = a0.x * b0.x + a0.y * b0.y + a0.z * b0.z + a0.w * b0.w
                  + a1.x * b1.x + a1.y * b1.y + a1.z * b1.z + a1.w * b1.w;
        float d02 = a0.x * c0.x + a0.y * c0.y + a0.z * c0.z + a0.w * c0.w
                  + a1.x * c1.x + a1.y * c1.y + a1.z * c1.z + a1.w * c1.w;
        float d12 = b0.x * c0.x + b0.y * c0.y + b0.z * c0.z + b0.w * c0.w
                  + b1.x * c1.x + b1.y * c1.y + b1.z * c1.z + b1.w * c1.w;
#pragma unroll
        for (int o = 16; o > 0; o >>= 1) {
            d01 += __shfl_xor_sync(0xffffffffu, d01, o);
            d02 += __shfl_xor_sync(0xffffffffu, d02, o);
            d12 += __shfl_xor_sync(0xffffffffu, d12, o);
        }
        if (lane == 0) {
            float e5 = __expf(5.0f);
            float s0 = 0.f, s1 = 0.f, s2 = 0.f;
#pragma unroll
            for (int o = 0; o < BLK; o++) {
                s0 += g_spart[1][o][3 * u + 0];
                s1 += g_spart[1][o][3 * u + 1];
                s2 += g_spart[1][o][3 * u + 2];
            }
            float per0 = logf(s0 - e5 + 1e-12f) - 2.5f * (d01 + d02);
            float per1 = logf(s1 - e5 + 1e-12f) - 2.5f * (d01 + d12);
            float per2 = logf(s2 - e5 + 1e-12f) - 2.5f * (d02 + d12);
            acc = per0 + per1 + per2;
        }
    }
    float r = blk_reduce(acc, sm);
    if (threadIdx.x == 0) g_un_part[blockIdx.x] = r;
}

// ---------------- final merge ----------------
__global__ void __launch_bounds__(256) final_kernel(float* __restrict__ out) {
    __shared__ float sm[256];
    int tid = threadIdx.x;
    float c0 = blk_reduce((tid < BCE_BLOCKS) ? g_bce_part[tid][0] : 0.f, sm);
    float c1 = blk_reduce((tid < BCE_BLOCKS) ? g_bce_part[tid][1] : 0.f, sm);
    float c2 = blk_reduce((tid < BCE_BLOCKS) ? g_bce_part[tid][2] : 0.f, sm);
    float c3 = blk_reduce((tid < BCE_BLOCKS) ? g_bce_part[tid][3] : 0.f, sm);
    float cnt = blk_reduce((tid < BCE_BLOCKS) ? g_bce_part[tid][4] : 0.f, sm);
    float sup_sum = blk_reduce((tid < 24) ? g_sup_part[tid] : 0.f, sm);
    float un_sum = blk_reduce(g_un_part[tid], sm);
    if (tid == 0) {
        float denom = fmaxf(cnt, 1.0f);
        float main_loss = c0 / denom;
        float view_loss = (c1 + c2 + c3) / (3.0f * denom);
        float sup_loss = sup_sum / (float)MM;
        float un_loss = un_sum / (float)MM;
        float total = main_loss + view_loss + sup_loss + 0.2f * un_loss;
        out[0] = total;
        out[1] = main_loss;
        out[2] = view_loss;
        out[3] = sup_loss;
        out[4] = un_loss;
    }
}

// ---------------- launch ----------------
extern "C" void kernel_launch(void* const* d_in, const int* in_sizes, int n_in,
                              void* d_out, int out_size) {
    const float* fused = (const float*)d_in[0];
    const float* vlg   = (const float*)d_in[1];
    const float* proj  = (const float*)d_in[2];
    const float* lab   = (const float*)d_in[3];
    const void*  maskp = d_in[4];
    const int*   pos   = (const int*)d_in[5];
    const int*   neg   = (const int*)d_in[6];
    const int*   unl   = (const int*)d_in[7];
    float* out = (float*)d_out;
    int n = in_sizes[0];

    cudaFuncSetAttribute(simmma_kernel, cudaFuncAttributeMaxDynamicSharedMemorySize, SMEM_DYN);

    detect_mask_kernel<<<1, 32>>>((const unsigned char*)maskp);
    bce_kernel<<<BCE_BLOCKS, 256>>>(fused, vlg, lab, maskp, n);
    gather_kernel<<<(2 * MM * 32) / 256, 256>>>(proj, pos, neg, unl);
    simmma_kernel<<<dim3(NTILE, 2), 1024, SMEM_DYN>>>();
    supfin_kernel<<<MM / 256, 256>>>();
    unfin_kernel<<<(UU * 32) / 256, 256>>>();
    final_kernel<<<1, 256>>>(out);
}

// round 8
// speedup vs baseline: 7.3221x; 2.2148x over previous
#include <cuda_runtime.h>
#include <cuda_bf16.h>
#include <stdint.h>

// ---------------- problem constants ----------------
#define NN      100000
#define DD      256
#define PP      1024
#define UU      2048
#define MM      6144          // rows per similarity matrix (2048*3)
#define BLK     48            // 6144/128 row blocks
#define NTILE   1176          // 48*49/2 upper-tri tiles
#define BCE_BLOCKS 128

#define PITCH   144           // padded smem row bytes (64 bf16 -> 128B + 16 pad)
#define STAGE_OP (128 * PITCH)        // 18432 bytes per tile
#define STAGE_SZ (2 * STAGE_OP)       // 36864 per stage (A, B)
#define NSTAGE  2
#define SMEM_DYN (NSTAGE * STAGE_SZ)  // 73728 -> 2 CTAs/SM

// ---------------- device scratch ----------------
__device__ __align__(16) __nv_bfloat16 g_img[2][MM][DD];  // bf16 rows per matrix
__device__ float4 g_zn[MM][64];                 // unsup renormalized fp32 rows
__device__ float  g_spart[2][BLK][MM];          // per-(otherblock,row) sum of exp
__device__ float  g_tpart[BLK][MM];             // per-(otherblock,row) sum of dot (sup)
__device__ float  g_bce_part[BCE_BLOCKS][5];
__device__ float  g_sup_part[24];
__device__ float  g_un_part[256];
__device__ int    g_maskmode;

// ---------------- helpers ----------------
__device__ __forceinline__ uint32_t smem_u32(const void* p) {
    uint32_t a;
    asm("{ .reg .u64 t; cvta.to.shared.u64 t, %1; cvt.u32.u64 %0, t; }" : "=r"(a) : "l"(p));
    return a;
}

__device__ __forceinline__ float blk_reduce(float v, float* sm) {
    int tid = threadIdx.x;
    sm[tid] = v; __syncthreads();
#pragma unroll
    for (int s = 128; s > 0; s >>= 1) {
        if (tid < s) sm[tid] += sm[tid + s];
        __syncthreads();
    }
    float r = sm[0]; __syncthreads();
    return r;
}

// ---------------- mask dtype detection ----------------
__global__ void detect_mask_kernel(const unsigned char* m) {
    if (threadIdx.x == 0 && blockIdx.x == 0) {
        bool nonbin = false, oddone = false;
        for (int i = 0; i < 256; i++) {
            unsigned char b = m[i];
            if (b > 1) nonbin = true;
            else if (b == 1 && (i & 3)) oddone = true;
        }
        g_maskmode = nonbin ? 2 : (oddone ? 1 : 0);
    }
}

// ---------------- BCE partial sums ----------------
__global__ void __launch_bounds__(256) bce_kernel(const float* __restrict__ fused,
                                                  const float* __restrict__ vlg,
                                                  const float* __restrict__ lab,
                                                  const void* __restrict__ maskp,
                                                  int n) {
    __shared__ float sm[256];
    int mode = g_maskmode;
    float s_main = 0.f, s_v0 = 0.f, s_v1 = 0.f, s_v2 = 0.f, s_cnt = 0.f;
    for (int i = blockIdx.x * blockDim.x + threadIdx.x; i < n; i += gridDim.x * blockDim.x) {
        float mv;
        if (mode == 2)      mv = (((const float*)maskp)[i] != 0.f) ? 1.f : 0.f;
        else if (mode == 1) mv = (((const unsigned char*)maskp)[i] != 0) ? 1.f : 0.f;
        else                mv = (((const int*)maskp)[i] != 0) ? 1.f : 0.f;
        if (mv != 0.f) {
            float y = lab[i];
            float x = fused[i];
            s_main += fmaxf(x, 0.f) - x * y + log1pf(__expf(-fabsf(x)));
            x = vlg[i];
            s_v0 += fmaxf(x, 0.f) - x * y + log1pf(__expf(-fabsf(x)));
            x = vlg[NN + i];
            s_v1 += fmaxf(x, 0.f) - x * y + log1pf(__expf(-fabsf(x)));
            x = vlg[2 * NN + i];
            s_v2 += fmaxf(x, 0.f) - x * y + log1pf(__expf(-fabsf(x)));
            s_cnt += 1.f;
        }
    }
    float r;
    r = blk_reduce(s_main, sm); if (threadIdx.x == 0) g_bce_part[blockIdx.x][0] = r;
    r = blk_reduce(s_v0, sm);   if (threadIdx.x == 0) g_bce_part[blockIdx.x][1] = r;
    r = blk_reduce(s_v1, sm);   if (threadIdx.x == 0) g_bce_part[blockIdx.x][2] = r;
    r = blk_reduce(s_v2, sm);   if (threadIdx.x == 0) g_bce_part[blockIdx.x][3] = r;
    r = blk_reduce(s_cnt, sm);  if (threadIdx.x == 0) g_bce_part[blockIdx.x][4] = r;
}

// ---------------- gather: bf16 rows ----------------
__device__ __forceinline__ void store_b16(int mat, int row, int k0, float4 v) {
    __nv_bfloat16 h0 = __float2bfloat16(v.x), h1 = __float2bfloat16(v.y);
    __nv_bfloat16 h2 = __float2bfloat16(v.z), h3 = __float2bfloat16(v.w);
    uint2 hp;
    hp.x = (uint32_t)__bfloat16_as_ushort(h0) | ((uint32_t)__bfloat16_as_ushort(h1) << 16);
    hp.y = (uint32_t)__bfloat16_as_ushort(h2) | ((uint32_t)__bfloat16_as_ushort(h3) << 16);
    *(uint2*)&g_img[mat][row][k0] = hp;
}

__global__ void __launch_bounds__(256) gather_kernel(const float* __restrict__ proj,
                                                     const int* __restrict__ pos,
                                                     const int* __restrict__ neg,
                                                     const int* __restrict__ unl) {
    int gw = (blockIdx.x * blockDim.x + threadIdx.x) >> 5;
    int lane = threadIdx.x & 31;
    if (gw >= 2 * MM) return;
    int mat = (gw >= MM) ? 1 : 0;
    int row = gw - mat * MM;
    int l = row / 3, v = row % 3;
    int idx;
    if (mat == 0) idx = (l < PP) ? pos[l] : neg[l - PP];
    else          idx = unl[l];
    const float4* src = (const float4*)(proj + ((size_t)v * NN + (size_t)idx) * DD);
    float4 x0 = src[lane];
    float4 x1 = src[lane + 32];
    if (mat == 1) {
        float ss = x0.x * x0.x + x0.y * x0.y + x0.z * x0.z + x0.w * x0.w
                 + x1.x * x1.x + x1.y * x1.y + x1.z * x1.z + x1.w * x1.w;
#pragma unroll
        for (int o = 16; o > 0; o >>= 1) ss += __shfl_xor_sync(0xffffffffu, ss, o);
        float inv = 1.f / (sqrtf(ss) + 1e-8f);
        x0.x *= inv; x0.y *= inv; x0.z *= inv; x0.w *= inv;
        x1.x *= inv; x1.y *= inv; x1.z *= inv; x1.w *= inv;
        g_zn[row][lane]      = x0;
        g_zn[row][lane + 32] = x1;
    }
    store_b16(mat, row, 4 * lane, x0);
    store_b16(mat, row, 128 + 4 * lane, x1);
}

// ---------------- HMMA similarity kernel (upper-triangular tiles) ----------------
// 1024 threads: 2048 x 16B per stage = 2 cp.async per thread.
__device__ __forceinline__ void load_stage(uint32_t sbase, int stage, int m, int I, int J,
                                           int kk, int tid) {
    const __nv_bfloat16* bA = &g_img[m][I * 128][kk * 64];
    const __nv_bfloat16* bB = &g_img[m][J * 128][kk * 64];
    uint32_t sb = sbase + stage * STAGE_SZ;
#pragma unroll
    for (int i = 0; i < 2; i++) {
        int idx = tid * 2 + i;
        int op = idx >> 10, rc = idx & 1023, row = rc >> 3, c16 = rc & 7;
        const __nv_bfloat16* src = (op ? bB : bA) + row * DD + c16 * 8;
        uint32_t dst = sb + op * STAGE_OP + row * PITCH + c16 * 16;
        asm volatile("cp.async.cg.shared.global [%0], [%1], 16;" :: "r"(dst), "l"(src));
    }
    asm volatile("cp.async.commit_group;" ::: "memory");
}

#define MMA8(CC, AA, B0, B1)                                                   \
    asm volatile(                                                              \
        "mma.sync.aligned.m16n8k16.row.col.f32.bf16.bf16.f32 "                 \
        "{%0,%1,%2,%3}, {%4,%5,%6,%7}, {%8,%9}, {%0,%1,%2,%3};"                \
        : "+f"((CC)[0]), "+f"((CC)[1]), "+f"((CC)[2]), "+f"((CC)[3])           \
        : "r"((AA)[0]), "r"((AA)[1]), "r"((AA)[2]), "r"((AA)[3]),              \
          "r"(B0), "r"(B1))

__global__ void __launch_bounds__(1024, 2) simmma_kernel() {
    extern __shared__ __align__(16) unsigned char smem[];
    const int tid = threadIdx.x, lane = tid & 31, wid = tid >> 5;
    const int wm = wid >> 3, wn = wid & 7;     // 4x8 warp grid; warp tile 32x16
    const int m = blockIdx.y;
    int t = blockIdx.x, I = 0;
    while (t >= BLK - I) { t -= BLK - I; I++; }
    const int J = I + t;
    uint32_t sbase = smem_u32(smem);

    float C[2][2][4];
#pragma unroll
    for (int a = 0; a < 2; a++)
#pragma unroll
        for (int b = 0; b < 2; b++)
#pragma unroll
            for (int c = 0; c < 4; c++) C[a][b][c] = 0.f;

    load_stage(sbase, 0, m, I, J, 0, tid);
    for (int kk = 0; kk < 4; kk++) {
        int buf = kk & 1;
        if (kk + 1 < 4) {
            load_stage(sbase, buf ^ 1, m, I, J, kk + 1, tid);
            asm volatile("cp.async.wait_group 1;" ::: "memory");
        } else {
            asm volatile("cp.async.wait_group 0;" ::: "memory");
        }
        __syncthreads();
        uint32_t AH = sbase + buf * STAGE_SZ;
        uint32_t BH = AH + STAGE_OP;
#pragma unroll
        for (int ks = 0; ks < 4; ks++) {
            uint32_t ah[2][4], bh[4];
#pragma unroll
            for (int mi = 0; mi < 2; mi++) {
                uint32_t off = (wm * 32 + mi * 16 + (lane & 15)) * PITCH
                             + (ks * 16 + (lane >> 4) * 8) * 2;
                asm volatile("ldmatrix.sync.aligned.m8n8.x4.shared.b16 {%0,%1,%2,%3}, [%4];"
                    : "=r"(ah[mi][0]), "=r"(ah[mi][1]), "=r"(ah[mi][2]), "=r"(ah[mi][3])
                    : "r"(AH + off));
            }
            {
                int g = lane >> 3;
                uint32_t off = (wn * 16 + (g >> 1) * 8 + (lane & 7)) * PITCH
                             + (ks * 16 + (g & 1) * 8) * 2;
                asm volatile("ldmatrix.sync.aligned.m8n8.x4.shared.b16 {%0,%1,%2,%3}, [%4];"
                    : "=r"(bh[0]), "=r"(bh[1]), "=r"(bh[2]), "=r"(bh[3]) : "r"(BH + off));
            }
#pragma unroll
            for (int mi = 0; mi < 2; mi++)
#pragma unroll
                for (int ni = 0; ni < 2; ni++) {
                    int q2 = ni * 2;
                    MMA8(C[mi][ni], ah[mi], bh[q2], bh[q2 + 1]);
                }
        }
        __syncthreads();
    }

    // ---------- epilogue: row/col exp & raw sums ----------
    const float OFF = (m == 0) ? 5.f : 0.f;
    const bool lm = (I < 24) == (J < 24);
    float rE[4], rR[4], cE[4], cR[4];
#pragma unroll
    for (int k = 0; k < 4; k++) { rE[k] = rR[k] = cE[k] = cR[k] = 0.f; }
#pragma unroll
    for (int mi = 0; mi < 2; mi++)
#pragma unroll
        for (int ni = 0; ni < 2; ni++)
#pragma unroll
            for (int f = 0; f < 4; f++) {
                int half = f >> 1, j = f & 1;
                float v = C[mi][ni][f];
                float e = __expf(5.f * v - OFF);
                rE[mi * 2 + half] += e; rR[mi * 2 + half] += v;
                cE[ni * 2 + j]    += e; cR[ni * 2 + j]    += v;
            }

    float* scRowE = (float*)smem;          // [128][8]
    float* scRowR = scRowE + 1024;         // [128][8]
    float* scColE = scRowR + 1024;         // [128][4]
    float* scColR = scColE + 512;          // [128][4]
#pragma unroll
    for (int k = 0; k < 4; k++) {
        float vE = rE[k], vR = rR[k];
        vE += __shfl_xor_sync(0xffffffffu, vE, 1);
        vE += __shfl_xor_sync(0xffffffffu, vE, 2);
        vR += __shfl_xor_sync(0xffffffffu, vR, 1);
        vR += __shfl_xor_sync(0xffffffffu, vR, 2);
        if ((lane & 3) == 0) {
            int r = wm * 32 + (k >> 1) * 16 + (k & 1) * 8 + (lane >> 2);
            scRowE[r * 8 + wn] = vE;
            scRowR[r * 8 + wn] = vR;
        }
    }
#pragma unroll
    for (int k = 0; k < 4; k++) {
        float vE = cE[k], vR = cR[k];
        vE += __shfl_xor_sync(0xffffffffu, vE, 4);
        vE += __shfl_xor_sync(0xffffffffu, vE, 8);
        vE += __shfl_xor_sync(0xffffffffu, vE, 16);
        vR += __shfl_xor_sync(0xffffffffu, vR, 4);
        vR += __shfl_xor_sync(0xffffffffu, vR, 8);
        vR += __shfl_xor_sync(0xffffffffu, vR, 16);
        if (lane < 4) {
            int cc = wn * 16 + (k >> 1) * 8 + (lane & 3) * 2 + (k & 1);
            scColE[cc * 4 + wm] = vE;
            scColR[cc * 4 + wm] = vR;
        }
    }
    __syncthreads();
    if (tid < 128) {
        int r = tid;
        float sE = 0.f, sR = 0.f;
#pragma unroll
        for (int x = 0; x < 8; x++) { sE += scRowE[r * 8 + x]; sR += scRowR[r * 8 + x]; }
        g_spart[m][J][I * 128 + r] = sE;
        if (m == 0) g_tpart[J][I * 128 + r] = lm ? sR : 0.f;
    } else if (tid < 256 && I != J) {
        int cc = tid - 128;
        float sE = scColE[cc * 4] + scColE[cc * 4 + 1] + scColE[cc * 4 + 2] + scColE[cc * 4 + 3];
        float sR = scColR[cc * 4] + scColR[cc * 4 + 1] + scColR[cc * 4 + 2] + scColR[cc * 4 + 3];
        g_spart[m][I][J * 128 + cc] = sE;
        if (m == 0) g_tpart[I][J * 128 + cc] = lm ? sR : 0.f;
    }
}

// ---------------- sup finalize ----------------
__global__ void __launch_bounds__(256) supfin_kernel() {
    __shared__ float sm[256];
    int row = blockIdx.x * 256 + threadIdx.x;  // 24 blocks
    float s = 0.f, t = 0.f;
#pragma unroll
    for (int o = 0; o < BLK; o++) { s += g_spart[0][o][row]; t += g_tpart[o][row]; }
    float denom = s - 1.0f + 1e-12f;           // remove diagonal exp(0)=1
    float loss = logf(denom) + 5.0f - (5.0f * t - 5.0f) / 3071.0f;
    float r = blk_reduce(loss, sm);
    if (threadIdx.x == 0) g_sup_part[blockIdx.x] = r;
}

// ---------------- unsup finalize ----------------
__global__ void __launch_bounds__(256) unfin_kernel() {
    __shared__ float sm[256];
    int gw = (blockIdx.x * 256 + threadIdx.x) >> 5;  // 2048 warps
    int lane = threadIdx.x & 31;
    float acc = 0.f;
    if (gw < UU) {
        int u = gw;
        const float4* r0 = g_zn[3 * u + 0];
        const float4* r1 = g_zn[3 * u + 1];
        const float4* r2 = g_zn[3 * u + 2];
        float4 a0 = r0[lane], a1 = r0[lane + 32];
        float4 b0 = r1[lane], b1 = r1[lane + 32];
        float4 c0 = r2[lane], c1 = r2[lane + 32];
        float d01 = a0.x * b0.x + a0.y * b0.y + a0.z * b0.z + a0.w * b0.w
                  + a1.x * b1.x + a1.y * b1.y + a1.z * b1.z + a1.w * b1.w;
        float d02 = a0.x * c0.x + a0.y * c0.y + a0.z * c0.z + a0.w * c0.w
                  + a1.x * c1.x + a1.y * c1.y + a1.z * c1.z + a1.w * c1.w;
        float d12 = b0.x * c0.x + b0.y * c0.y + b0.z * c0.z + b0.w * c0.w
                  + b1.x * c1.x + b1.y * c1.y + b1.z * c1.z + b1.w * c1.w;
#pragma unroll
        for (int o = 16; o > 0; o >>= 1) {
            d01 += __shfl_xor_sync(0xffffffffu, d01, o);
            d02 += __shfl_xor_sync(0xffffffffu, d02, o);
            d12 += __shfl_xor_sync(0xffffffffu, d12, o);
        }
        if (lane == 0) {
            float e5 = __expf(5.0f);
            float s0 = 0.f, s1 = 0.f, s2 = 0.f;
#pragma unroll
            for (int o = 0; o < BLK; o++) {
                s0 += g_spart[1][o][3 * u + 0];
                s1 += g_spart[1][o][3 * u + 1];
                s2 += g_spart[1][o][3 * u + 2];
            }
            float per0 = logf(s0 - e5 + 1e-12f) - 2.5f * (d01 + d02);
            float per1 = logf(s1 - e5 + 1e-12f) - 2.5f * (d01 + d12);
            float per2 = logf(s2 - e5 + 1e-12f) - 2.5f * (d02 + d12);
            acc = per0 + per1 + per2;
        }
    }
    float r = blk_reduce(acc, sm);
    if (threadIdx.x == 0) g_un_part[blockIdx.x] = r;
}

// ---------------- final merge ----------------
__global__ void __launch_bounds__(256) final_kernel(float* __restrict__ out) {
    __shared__ float sm[256];
    int tid = threadIdx.x;
    float c0 = blk_reduce((tid < BCE_BLOCKS) ? g_bce_part[tid][0] : 0.f, sm);
    float c1 = blk_reduce((tid < BCE_BLOCKS) ? g_bce_part[tid][1] : 0.f, sm);
    float c2 = blk_reduce((tid < BCE_BLOCKS) ? g_bce_part[tid][2] : 0.f, sm);
    float c3 = blk_reduce((tid < BCE_BLOCKS) ? g_bce_part[tid][3] : 0.f, sm);
    float cnt = blk_reduce((tid < BCE_BLOCKS) ? g_bce_part[tid][4] : 0.f, sm);
    float sup_sum = blk_reduce((tid < 24) ? g_sup_part[tid] : 0.f, sm);
    float un_sum = blk_reduce(g_un_part[tid], sm);
    if (tid == 0) {
        float denom = fmaxf(cnt, 1.0f);
        float main_loss = c0 / denom;
        float view_loss = (c1 + c2 + c3) / (3.0f * denom);
        float sup_loss = sup_sum / (float)MM;
        float un_loss = un_sum / (float)MM;
        float total = main_loss + view_loss + sup_loss + 0.2f * un_loss;
        out[0] = total;
        out[1] = main_loss;
        out[2] = view_loss;
        out[3] = sup_loss;
        out[4] = un_loss;
    }
}

// ---------------- launch ----------------
extern "C" void kernel_launch(void* const* d_in, const int* in_sizes, int n_in,
                              void* d_out, int out_size) {
    const float* fused = (const float*)d_in[0];
    const float* vlg   = (const float*)d_in[1];
    const float* proj  = (const float*)d_in[2];
    const float* lab   = (const float*)d_in[3];
    const void*  maskp = d_in[4];
    const int*   pos   = (const int*)d_in[5];
    const int*   neg   = (const int*)d_in[6];
    const int*   unl   = (const int*)d_in[7];
    float* out = (float*)d_out;
    int n = in_sizes[0];

    cudaFuncSetAttribute(simmma_kernel, cudaFuncAttributeMaxDynamicSharedMemorySize, SMEM_DYN);

    detect_mask_kernel<<<1, 32>>>((const unsigned char*)maskp);
    bce_kernel<<<BCE_BLOCKS, 256>>>(fused, vlg, lab, maskp, n);
    gather_kernel<<<(2 * MM * 32) / 256, 256>>>(proj, pos, neg, unl);
    simmma_kernel<<<dim3(NTILE, 2), 1024, SMEM_DYN>>>();
    supfin_kernel<<<MM / 256, 256>>>();
    unfin_kernel<<<(UU * 32) / 256, 256>>>();
    final_kernel<<<1, 256>>>(out);
}

// round 9
// speedup vs baseline: 7.5697x; 1.0338x over previous
#include <cuda_runtime.h>
#include <cuda_bf16.h>
#include <stdint.h>

// ---------------- problem constants ----------------
#define NN      100000
#define DD      256
#define PP      1024
#define UU      2048
#define MM      6144          // rows per similarity matrix (2048*3)
#define BLK     48            // 6144/128 row blocks
#define NTILE   1176          // 48*49/2 upper-tri tiles
#define BCE_BLOCKS 128

#define PITCH   144           // padded smem row bytes (64 bf16 -> 128B + 16 pad)
#define STAGE_OP (128 * PITCH)        // 18432 bytes per tile
#define STAGE_SZ (2 * STAGE_OP)       // 36864 per stage (A, B)
#define NSTAGE  2
#define SMEM_DYN (NSTAGE * STAGE_SZ)  // 73728 -> 2 CTAs/SM (smem+regs both fit)

// ---------------- device scratch ----------------
__device__ __align__(16) __nv_bfloat16 g_img[2][MM][DD];  // bf16 rows per matrix
__device__ float4 g_zn[MM][64];                 // unsup renormalized fp32 rows
__device__ float  g_spart[2][BLK][MM];          // per-(otherblock,row) sum of exp
__device__ float  g_tpart[BLK][MM];             // per-(otherblock,row) sum of dot (sup)
__device__ float  g_bce_part[BCE_BLOCKS][5];
__device__ float  g_sup_part[24];
__device__ float  g_un_part[256];
__device__ int    g_maskmode;

// ---------------- helpers ----------------
__device__ __forceinline__ uint32_t smem_u32(const void* p) {
    uint32_t a;
    asm("{ .reg .u64 t; cvta.to.shared.u64 t, %1; cvt.u32.u64 %0, t; }" : "=r"(a) : "l"(p));
    return a;
}

__device__ __forceinline__ float blk_reduce(float v, float* sm) {
    int tid = threadIdx.x;
    sm[tid] = v; __syncthreads();
#pragma unroll
    for (int s = 128; s > 0; s >>= 1) {
        if (tid < s) sm[tid] += sm[tid + s];
        __syncthreads();
    }
    float r = sm[0]; __syncthreads();
    return r;
}

// ---------------- mask dtype detection ----------------
__global__ void detect_mask_kernel(const unsigned char* m) {
    if (threadIdx.x == 0 && blockIdx.x == 0) {
        bool nonbin = false, oddone = false;
        for (int i = 0; i < 256; i++) {
            unsigned char b = m[i];
            if (b > 1) nonbin = true;
            else if (b == 1 && (i & 3)) oddone = true;
        }
        g_maskmode = nonbin ? 2 : (oddone ? 1 : 0);
    }
}

// ---------------- BCE partial sums ----------------
__global__ void __launch_bounds__(256) bce_kernel(const float* __restrict__ fused,
                                                  const float* __restrict__ vlg,
                                                  const float* __restrict__ lab,
                                                  const void* __restrict__ maskp,
                                                  int n) {
    __shared__ float sm[256];
    int mode = g_maskmode;
    float s_main = 0.f, s_v0 = 0.f, s_v1 = 0.f, s_v2 = 0.f, s_cnt = 0.f;
    for (int i = blockIdx.x * blockDim.x + threadIdx.x; i < n; i += gridDim.x * blockDim.x) {
        float mv;
        if (mode == 2)      mv = (((const float*)maskp)[i] != 0.f) ? 1.f : 0.f;
        else if (mode == 1) mv = (((const unsigned char*)maskp)[i] != 0) ? 1.f : 0.f;
        else                mv = (((const int*)maskp)[i] != 0) ? 1.f : 0.f;
        if (mv != 0.f) {
            float y = lab[i];
            float x = fused[i];
            s_main += fmaxf(x, 0.f) - x * y + log1pf(__expf(-fabsf(x)));
            x = vlg[i];
            s_v0 += fmaxf(x, 0.f) - x * y + log1pf(__expf(-fabsf(x)));
            x = vlg[NN + i];
            s_v1 += fmaxf(x, 0.f) - x * y + log1pf(__expf(-fabsf(x)));
            x = vlg[2 * NN + i];
            s_v2 += fmaxf(x, 0.f) - x * y + log1pf(__expf(-fabsf(x)));
            s_cnt += 1.f;
        }
    }
    float r;
    r = blk_reduce(s_main, sm); if (threadIdx.x == 0) g_bce_part[blockIdx.x][0] = r;
    r = blk_reduce(s_v0, sm);   if (threadIdx.x == 0) g_bce_part[blockIdx.x][1] = r;
    r = blk_reduce(s_v1, sm);   if (threadIdx.x == 0) g_bce_part[blockIdx.x][2] = r;
    r = blk_reduce(s_v2, sm);   if (threadIdx.x == 0) g_bce_part[blockIdx.x][3] = r;
    r = blk_reduce(s_cnt, sm);  if (threadIdx.x == 0) g_bce_part[blockIdx.x][4] = r;
}

// ---------------- gather: bf16 rows ----------------
__device__ __forceinline__ void store_b16(int mat, int row, int k0, float4 v) {
    __nv_bfloat16 h0 = __float2bfloat16(v.x), h1 = __float2bfloat16(v.y);
    __nv_bfloat16 h2 = __float2bfloat16(v.z), h3 = __float2bfloat16(v.w);
    uint2 hp;
    hp.x = (uint32_t)__bfloat16_as_ushort(h0) | ((uint32_t)__bfloat16_as_ushort(h1) << 16);
    hp.y = (uint32_t)__bfloat16_as_ushort(h2) | ((uint32_t)__bfloat16_as_ushort(h3) << 16);
    *(uint2*)&g_img[mat][row][k0] = hp;
}

__global__ void __launch_bounds__(256) gather_kernel(const float* __restrict__ proj,
                                                     const int* __restrict__ pos,
                                                     const int* __restrict__ neg,
                                                     const int* __restrict__ unl) {
    int gw = (blockIdx.x * blockDim.x + threadIdx.x) >> 5;
    int lane = threadIdx.x & 31;
    if (gw >= 2 * MM) return;
    int mat = (gw >= MM) ? 1 : 0;
    int row = gw - mat * MM;
    int l = row / 3, v = row % 3;
    int idx;
    if (mat == 0) idx = (l < PP) ? pos[l] : neg[l - PP];
    else          idx = unl[l];
    const float4* src = (const float4*)(proj + ((size_t)v * NN + (size_t)idx) * DD);
    float4 x0 = src[lane];
    float4 x1 = src[lane + 32];
    if (mat == 1) {
        float ss = x0.x * x0.x + x0.y * x0.y + x0.z * x0.z + x0.w * x0.w
                 + x1.x * x1.x + x1.y * x1.y + x1.z * x1.z + x1.w * x1.w;
#pragma unroll
        for (int o = 16; o > 0; o >>= 1) ss += __shfl_xor_sync(0xffffffffu, ss, o);
        float inv = 1.f / (sqrtf(ss) + 1e-8f);
        x0.x *= inv; x0.y *= inv; x0.z *= inv; x0.w *= inv;
        x1.x *= inv; x1.y *= inv; x1.z *= inv; x1.w *= inv;
        g_zn[row][lane]      = x0;
        g_zn[row][lane + 32] = x1;
    }
    store_b16(mat, row, 4 * lane, x0);
    store_b16(mat, row, 128 + 4 * lane, x1);
}

// ---------------- HMMA similarity kernel (upper-triangular tiles) ----------------
// 512 threads: 2048 x 16B per stage = 4 cp.async per thread.
__device__ __forceinline__ void load_stage(uint32_t sbase, int stage, int m, int I, int J,
                                           int kk, int tid) {
    const __nv_bfloat16* bA = &g_img[m][I * 128][kk * 64];
    const __nv_bfloat16* bB = &g_img[m][J * 128][kk * 64];
    uint32_t sb = sbase + stage * STAGE_SZ;
#pragma unroll
    for (int i = 0; i < 4; i++) {
        int idx = tid * 4 + i;
        int op = idx >> 10, rc = idx & 1023, row = rc >> 3, c16 = rc & 7;
        const __nv_bfloat16* src = (op ? bB : bA) + row * DD + c16 * 8;
        uint32_t dst = sb + op * STAGE_OP + row * PITCH + c16 * 16;
        asm volatile("cp.async.cg.shared.global [%0], [%1], 16;" :: "r"(dst), "l"(src));
    }
    asm volatile("cp.async.commit_group;" ::: "memory");
}

#define MMA8(CC, AA, B0, B1)                                                   \
    asm volatile(                                                              \
        "mma.sync.aligned.m16n8k16.row.col.f32.bf16.bf16.f32 "                 \
        "{%0,%1,%2,%3}, {%4,%5,%6,%7}, {%8,%9}, {%0,%1,%2,%3};"                \
        : "+f"((CC)[0]), "+f"((CC)[1]), "+f"((CC)[2]), "+f"((CC)[3])           \
        : "r"((AA)[0]), "r"((AA)[1]), "r"((AA)[2]), "r"((AA)[3]),              \
          "r"(B0), "r"(B1))

__global__ void __launch_bounds__(512, 2) simmma_kernel() {
    extern __shared__ __align__(16) unsigned char smem[];
    const int tid = threadIdx.x, lane = tid & 31, wid = tid >> 5;
    const int wm = wid >> 2, wn = wid & 3;     // 4x4 warp grid; warp tile 32x32
    const int m = blockIdx.y;
    int t = blockIdx.x, I = 0;
    while (t >= BLK - I) { t -= BLK - I; I++; }
    const int J = I + t;
    uint32_t sbase = smem_u32(smem);

    float C[2][4][4];
#pragma unroll
    for (int a = 0; a < 2; a++)
#pragma unroll
        for (int b = 0; b < 4; b++)
#pragma unroll
            for (int c = 0; c < 4; c++) C[a][b][c] = 0.f;

    load_stage(sbase, 0, m, I, J, 0, tid);
    for (int kk = 0; kk < 4; kk++) {
        int buf = kk & 1;
        if (kk + 1 < 4) {
            load_stage(sbase, buf ^ 1, m, I, J, kk + 1, tid);
            asm volatile("cp.async.wait_group 1;" ::: "memory");
        } else {
            asm volatile("cp.async.wait_group 0;" ::: "memory");
        }
        __syncthreads();
        uint32_t AH = sbase + buf * STAGE_SZ;
        uint32_t BH = AH + STAGE_OP;
#pragma unroll
        for (int ks = 0; ks < 4; ks++) {
            uint32_t ah[2][4], bh[2][4];
#pragma unroll
            for (int mi = 0; mi < 2; mi++) {
                uint32_t off = (wm * 32 + mi * 16 + (lane & 15)) * PITCH
                             + (ks * 16 + (lane >> 4) * 8) * 2;
                asm volatile("ldmatrix.sync.aligned.m8n8.x4.shared.b16 {%0,%1,%2,%3}, [%4];"
                    : "=r"(ah[mi][0]), "=r"(ah[mi][1]), "=r"(ah[mi][2]), "=r"(ah[mi][3])
                    : "r"(AH + off));
            }
#pragma unroll
            for (int nP = 0; nP < 2; nP++) {
                int g = lane >> 3;
                uint32_t off = (wn * 32 + (nP * 2 + (g >> 1)) * 8 + (lane & 7)) * PITCH
                             + (ks * 16 + (g & 1) * 8) * 2;
                asm volatile("ldmatrix.sync.aligned.m8n8.x4.shared.b16 {%0,%1,%2,%3}, [%4];"
                    : "=r"(bh[nP][0]), "=r"(bh[nP][1]), "=r"(bh[nP][2]), "=r"(bh[nP][3])
                    : "r"(BH + off));
            }
#pragma unroll
            for (int mi = 0; mi < 2; mi++)
#pragma unroll
                for (int ni = 0; ni < 4; ni++) {
                    int p = ni >> 1, q2 = (ni & 1) * 2;
                    MMA8(C[mi][ni], ah[mi], bh[p][q2], bh[p][q2 + 1]);
                }
        }
        __syncthreads();
    }

    // ---------- epilogue: row/col exp & raw sums ----------
    const float OFF = (m == 0) ? 5.f : 0.f;
    const bool lm = (I < 24) == (J < 24);
    float rE[4], rR[4], cE[8], cR[8];
#pragma unroll
    for (int k = 0; k < 4; k++) { rE[k] = rR[k] = 0.f; }
#pragma unroll
    for (int k = 0; k < 8; k++) { cE[k] = cR[k] = 0.f; }
#pragma unroll
    for (int mi = 0; mi < 2; mi++)
#pragma unroll
        for (int ni = 0; ni < 4; ni++)
#pragma unroll
            for (int f = 0; f < 4; f++) {
                int half = f >> 1, j = f & 1;
                float v = C[mi][ni][f];
                float e = __expf(5.f * v - OFF);
                rE[mi * 2 + half] += e; rR[mi * 2 + half] += v;
                cE[ni * 2 + j]    += e; cR[ni * 2 + j]    += v;
            }

    float* scRowE = (float*)smem;          // [128][4]
    float* scRowR = scRowE + 512;          // [128][4]
    float* scColE = scRowR + 512;          // [128][4]
    float* scColR = scColE + 512;          // [128][4]
#pragma unroll
    for (int k = 0; k < 4; k++) {
        float vE = rE[k], vR = rR[k];
        vE += __shfl_xor_sync(0xffffffffu, vE, 1);
        vE += __shfl_xor_sync(0xffffffffu, vE, 2);
        vR += __shfl_xor_sync(0xffffffffu, vR, 1);
        vR += __shfl_xor_sync(0xffffffffu, vR, 2);
        if ((lane & 3) == 0) {
            int r = wm * 32 + (k >> 1) * 16 + (k & 1) * 8 + (lane >> 2);
            scRowE[r * 4 + wn] = vE;
            scRowR[r * 4 + wn] = vR;
        }
    }
#pragma unroll
    for (int k = 0; k < 8; k++) {
        float vE = cE[k], vR = cR[k];
        vE += __shfl_xor_sync(0xffffffffu, vE, 4);
        vE += __shfl_xor_sync(0xffffffffu, vE, 8);
        vE += __shfl_xor_sync(0xffffffffu, vE, 16);
        vR += __shfl_xor_sync(0xffffffffu, vR, 4);
        vR += __shfl_xor_sync(0xffffffffu, vR, 8);
        vR += __shfl_xor_sync(0xffffffffu, vR, 16);
        if (lane < 4) {
            int cc = wn * 32 + (k >> 1) * 8 + (lane & 3) * 2 + (k & 1);
            scColE[cc * 4 + wm] = vE;
            scColR[cc * 4 + wm] = vR;
        }
    }
    __syncthreads();
    if (tid < 128) {
        int r = tid;
        float sE = scRowE[r * 4] + scRowE[r * 4 + 1] + scRowE[r * 4 + 2] + scRowE[r * 4 + 3];
        float sR = scRowR[r * 4] + scRowR[r * 4 + 1] + scRowR[r * 4 + 2] + scRowR[r * 4 + 3];
        g_spart[m][J][I * 128 + r] = sE;
        if (m == 0) g_tpart[J][I * 128 + r] = lm ? sR : 0.f;
    } else if (tid < 256 && I != J) {
        int cc = tid - 128;
        float sE = scColE[cc * 4] + scColE[cc * 4 + 1] + scColE[cc * 4 + 2] + scColE[cc * 4 + 3];
        float sR = scColR[cc * 4] + scColR[cc * 4 + 1] + scColR[cc * 4 + 2] + scColR[cc * 4 + 3];
        g_spart[m][I][J * 128 + cc] = sE;
        if (m == 0) g_tpart[I][J * 128 + cc] = lm ? sR : 0.f;
    }
}

// ---------------- sup finalize ----------------
__global__ void __launch_bounds__(256) supfin_kernel() {
    __shared__ float sm[256];
    int row = blockIdx.x * 256 + threadIdx.x;  // 24 blocks
    float s = 0.f, t = 0.f;
#pragma unroll
    for (int o = 0; o < BLK; o++) { s += g_spart[0][o][row]; t += g_tpart[o][row]; }
    float denom = s - 1.0f + 1e-12f;           // remove diagonal exp(0)=1
    float loss = logf(denom) + 5.0f - (5.0f * t - 5.0f) / 3071.0f;
    float r = blk_reduce(loss, sm);
    if (threadIdx.x == 0) g_sup_part[blockIdx.x] = r;
}

// ---------------- unsup finalize ----------------
__global__ void __launch_bounds__(256) unfin_kernel() {
    __shared__ float sm[256];
    int gw = (blockIdx.x * 256 + threadIdx.x) >> 5;  // 2048 warps
    int lane = threadIdx.x & 31;
    float acc = 0.f;
    if (gw < UU) {
        int u = gw;
        const float4* r0 = g_zn[3 * u + 0];
        const float4* r1 = g_zn[3 * u + 1];
        const float4* r2 = g_zn[3 * u + 2];
        float4 a0 = r0[lane], a1 = r0[lane + 32];
        float4 b0 = r1[lane], b1 = r1[lane + 32];
        float4 c0 = r2[lane], c1 = r2[lane + 32];
        float d01 = a0.x * b0.x + a0.y * b0.y + a0.z * b0.z + a0.w * b0.w
                  + a1.x * b1.x + a1.y * b1.y + a1.z * b1.z + a1.w * b1.w;
        float d02 = a0.x * c0.x + a0.y * c0.y + a0.z * c0.z + a0.w * c0.w
                  + a1.x * c1.x + a1.y * c1.y + a1.z * c1.z + a1.w * c1.w;
        float d12 = b0.x * c0.x + b0.y * c0.y + b0.z * c0.z + b0.w * c0.w
                  + b1.x * c1.x + b1.y * c1.y + b1.z * c1.z + b1.w * c1.w;
#pragma unroll
        for (int o = 16; o > 0; o >>= 1) {
            d01 += __shfl_xor_sync(0xffffffffu, d01, o);
            d02 += __shfl_xor_sync(0xffffffffu, d02, o);
            d12 += __shfl_xor_sync(0xffffffffu, d12, o);
        }
        if (lane == 0) {
            float e5 = __expf(5.0f);
            float s0 = 0.f, s1 = 0.f, s2 = 0.f;
#pragma unroll
            for (int o = 0; o < BLK; o++) {
                s0 += g_spart[1][o][3 * u + 0];
                s1 += g_spart[1][o][3 * u + 1];
                s2 += g_spart[1][o][3 * u + 2];
            }
            float per0 = logf(s0 - e5 + 1e-12f) - 2.5f * (d01 + d02);
            float per1 = logf(s1 - e5 + 1e-12f) - 2.5f * (d01 + d12);
            float per2 = logf(s2 - e5 + 1e-12f) - 2.5f * (d02 + d12);
            acc = per0 + per1 + per2;
        }
    }
    float r = blk_reduce(acc, sm);
    if (threadIdx.x == 0) g_un_part[blockIdx.x] = r;
}

// ---------------- final merge ----------------
__global__ void __launch_bounds__(256) final_kernel(float* __restrict__ out) {
    __shared__ float sm[256];
    int tid = threadIdx.x;
    float c0 = blk_reduce((tid < BCE_BLOCKS) ? g_bce_part[tid][0] : 0.f, sm);
    float c1 = blk_reduce((tid < BCE_BLOCKS) ? g_bce_part[tid][1] : 0.f, sm);
    float c2 = blk_reduce((tid < BCE_BLOCKS) ? g_bce_part[tid][2] : 0.f, sm);
    float c3 = blk_reduce((tid < BCE_BLOCKS) ? g_bce_part[tid][3] : 0.f, sm);
    float cnt = blk_reduce((tid < BCE_BLOCKS) ? g_bce_part[tid][4] : 0.f, sm);
    float sup_sum = blk_reduce((tid < 24) ? g_sup_part[tid] : 0.f, sm);
    float un_sum = blk_reduce(g_un_part[tid], sm);
    if (tid == 0) {
        float denom = fmaxf(cnt, 1.0f);
        float main_loss = c0 / denom;
        float view_loss = (c1 + c2 + c3) / (3.0f * denom);
        float sup_loss = sup_sum / (float)MM;
        float un_loss = un_sum / (float)MM;
        float total = main_loss + view_loss + sup_loss + 0.2f * un_loss;
        out[0] = total;
        out[1] = main_loss;
        out[2] = view_loss;
        out[3] = sup_loss;
        out[4] = un_loss;
    }
}

// ---------------- launch ----------------
extern "C" void kernel_launch(void* const* d_in, const int* in_sizes, int n_in,
                              void* d_out, int out_size) {
    const float* fused = (const float*)d_in[0];
    const float* vlg   = (const float*)d_in[1];
    const float* proj  = (const float*)d_in[2];
    const float* lab   = (const float*)d_in[3];
    const void*  maskp = d_in[4];
    const int*   pos   = (const int*)d_in[5];
    const int*   neg   = (const int*)d_in[6];
    const int*   unl   = (const int*)d_in[7];
    float* out = (float*)d_out;
    int n = in_sizes[0];

    cudaFuncSetAttribute(simmma_kernel, cudaFuncAttributeMaxDynamicSharedMemorySize, SMEM_DYN);

    detect_mask_kernel<<<1, 32>>>((const unsigned char*)maskp);
    bce_kernel<<<BCE_BLOCKS, 256>>>(fused, vlg, lab, maskp, n);
    gather_kernel<<<(2 * MM * 32) / 256, 256>>>(proj, pos, neg, unl);
    simmma_kernel<<<dim3(NTILE, 2), 512, SMEM_DYN>>>();
    supfin_kernel<<<MM / 256, 256>>>();
    unfin_kernel<<<(UU * 32) / 256, 256>>>();
    final_kernel<<<1, 256>>>(out);
}